// round 13
// baseline (speedup 1.0000x reference)
#include <cuda_runtime.h>
#include <cuda_fp16.h>

#define BQ 4096
#define LE 2048
#define EE 128
#define KCB 2048
#define NROWS 65536

// ---- scratch ---------------------------------------------------------------
__device__ float  g_x1 [BQ * EE];
__device__ __half g_x1h[BQ * EE];
__device__ __half g_x1l[BQ * EE];
__device__ float  g_bf [BQ * LE];          // split-K partial scratch
__device__ __half g_h1 [BQ * LE];
__device__ __half g_l1 [BQ * LE];
__device__ __half g_h2 [BQ * LE];
__device__ __half g_l2 [BQ * LE];
__device__ __half g_w2h[LE * EE],  g_w2l[LE * EE];
__device__ __half g_w3h[LE * LE],  g_w3l[LE * LE];
__device__ __half g_w4h[LE * LE],  g_w4l[LE * LE];
__device__ __half g_d1h[LE * LE],  g_d1l[LE * LE];
__device__ __half g_d2h[LE * LE],  g_d2l[LE * LE];
__device__ __half g_d3h[EE * LE],  g_d3l[EE * LE];
__device__ __half g_cbh[KCB * EE], g_cbl[KCB * EE];
__device__ float  g_cbn[KCB];
__device__ int    g_maxnI;                 // max ||c||^2 (bits of positive float)

__device__ __forceinline__ float lrelu(float v) { return fmaxf(v, 0.2f * v); }

__device__ __forceinline__ void f16split(float x, __half& h, __half& l) {
    h = __float2half_rn(x);
    l = __float2half_rn(x - __half2float(h));
}
__device__ __forceinline__ unsigned sm_u32(const void* p) {
    return (unsigned)__cvta_generic_to_shared(p);
}
__device__ __forceinline__ void cp16(unsigned s, const void* g) {
    asm volatile("cp.async.cg.shared.global [%0], [%1], 16;" :: "r"(s), "l"(g));
}
__device__ __forceinline__ void cp_commit() { asm volatile("cp.async.commit_group;"); }
template<int N> __device__ __forceinline__ void cp_wait() {
    asm volatile("cp.async.wait_group %0;" :: "n"(N));
}
__device__ __forceinline__ void hmma(float* c, const unsigned* a, const unsigned* b) {
    asm volatile(
        "mma.sync.aligned.m16n8k16.row.col.f32.f16.f16.f32 "
        "{%0,%1,%2,%3}, {%4,%5,%6,%7}, {%8,%9}, {%0,%1,%2,%3};"
        : "+f"(c[0]), "+f"(c[1]), "+f"(c[2]), "+f"(c[3])
        : "r"(a[0]), "r"(a[1]), "r"(a[2]), "r"(a[3]), "r"(b[0]), "r"(b[1]));
}
__device__ __forceinline__ void ldsm4(unsigned* r, unsigned addr) {
    asm volatile("ldmatrix.sync.aligned.m8n8.x4.shared.b16 {%0,%1,%2,%3}, [%4];"
        : "=r"(r[0]), "=r"(r[1]), "=r"(r[2]), "=r"(r[3]) : "r"(addr));
}
// top-3 sorted insert (strict <, ascending-index arrival preserves first-index ties)
__device__ __forceinline__ void ins3(float* b, int* ix, float d, int c) {
    if (d < b[2]) {
        if (d < b[1]) {
            b[2] = b[1]; ix[2] = ix[1];
            if (d < b[0]) { b[1] = b[0]; ix[1] = ix[0]; b[0] = d; ix[0] = c; }
            else { b[1] = d; ix[1] = c; }
        } else { b[2] = d; ix[2] = c; }
    }
}
// ---- packed fp32x2 (skinny FFMA path) --------------------------------------
__device__ __forceinline__ unsigned long long pack2(float lo, float hi) {
    unsigned long long r;
    asm("mov.b64 %0, {%1, %2};" : "=l"(r) : "f"(lo), "f"(hi));
    return r;
}
__device__ __forceinline__ void fma2(unsigned long long& a,
                                     unsigned long long x, unsigned long long y) {
    asm("fma.rn.f32x2 %0, %1, %2, %0;" : "+l"(a) : "l"(x), "l"(y));
}
__device__ __forceinline__ float2 unpack2(unsigned long long v) {
    float lo, hi;
    asm("mov.b64 {%0, %1}, %2;" : "=f"(lo), "=f"(hi) : "l"(v));
    return make_float2(lo, hi);
}

// ---------------------------------------------------------------------------
// prep
// ---------------------------------------------------------------------------
__global__ void wtsplit_kernel(const float* __restrict__ W, __half* __restrict__ Th,
                               __half* __restrict__ Tl, int K, int N) {
    __shared__ float t[64][33];
    int n0 = blockIdx.x * 32, k0 = blockIdx.y * 64;
    int tx = threadIdx.x & 31, tr = threadIdx.x >> 5;
    for (int r = tr; r < 64; r += 8) t[r][tx] = W[(size_t)(k0 + r) * N + n0 + tx];
    __syncthreads();
    for (int r2 = tr; r2 < 32; r2 += 8) {
        __half h0, l0, h1, l1;
        f16split(t[2 * tx][r2], h0, l0);
        f16split(t[2 * tx + 1][r2], h1, l1);
        *(__half2*)&Th[(size_t)(n0 + r2) * K + k0 + 2 * tx] = __halves2half2(h0, h1);
        *(__half2*)&Tl[(size_t)(n0 + r2) * K + k0 + 2 * tx] = __halves2half2(l0, l1);
    }
}
__global__ void cbsplit_kernel(const float* __restrict__ cb, __half* __restrict__ hi,
                               __half* __restrict__ lo, float* __restrict__ nrm) {
    int n = blockIdx.x, e = threadIdx.x;
    float v = cb[n * EE + e];
    __half h, l; f16split(v, h, l);
    hi[n * EE + e] = h;
    lo[n * EE + e] = l;
    float q = v * v;
    #pragma unroll
    for (int o = 16; o > 0; o >>= 1) q += __shfl_xor_sync(0xFFFFFFFFu, q, o);
    __shared__ float ws[4];
    if ((e & 31) == 0) ws[e >> 5] = q;
    __syncthreads();
    if (e == 0) {
        float nn = ws[0] + ws[1] + ws[2] + ws[3];
        nrm[n] = nn;
        atomicMax(&g_maxnI, __float_as_int(nn));   // positive floats: int order ok
    }
}

// ---------------------------------------------------------------------------
// FP16 dense (R10 config): 128 threads, 4 warps (2x2 of 64x64), BK=32.
// ---------------------------------------------------------------------------
#define DPIT   80
#define DPLANE 10240
#define DBUF   40960
#define DSMEM  81920

__global__ __launch_bounds__(128, 2) void hmma_dense(
    const __half* __restrict__ Ah, const __half* __restrict__ Al,
    const __half* __restrict__ Bh, const __half* __restrict__ Bl,
    const float* __restrict__ bias,
    float* __restrict__ Cf, __half* __restrict__ Ch, __half* __restrict__ Cl,
    int M, int N, int K)
{
    extern __shared__ char dsm[];
    unsigned smb = sm_u32(dsm);
    int tid = threadIdx.x, lane = tid & 31, wid = tid >> 5;
    int wm = wid >> 1, wn = wid & 1, g = lane >> 2, tig = lane & 3;
    int bm = blockIdx.y * 128, bn = blockIdx.x * 128;
    bool aLo = (Al != nullptr), bLo = (Bl != nullptr);

    const __half* P[4] = { Ah + (size_t)bm * K, aLo ? Al + (size_t)bm * K : nullptr,
                           Bh + (size_t)bn * K, bLo ? Bl + (size_t)bn * K : nullptr };

    float acc[4][8][4];
    #pragma unroll
    for (int i = 0; i < 4; i++)
        #pragma unroll
        for (int j = 0; j < 8; j++)
            #pragma unroll
            for (int q = 0; q < 4; q++) acc[i][j][q] = 0.f;

    unsigned aBase = (wm * 64 + (lane & 15)) * DPIT + ((lane >> 4) & 1) * 16;
    unsigned bBase = 2 * DPLANE + (wn * 64 + ((lane >> 4) & 1) * 8 + (lane & 7)) * DPIT
                     + ((lane >> 3) & 1) * 16;

    auto load_stage = [&](int u, int b) {
        #pragma unroll
        for (int i = 0; i < 16; i++) {
            int cid = i * 128 + tid;
            int p = cid >> 9, rem = cid & 511, row = rem >> 2, c = rem & 3;
            if (P[p])
                cp16(smb + b * DBUF + p * DPLANE + row * DPIT + c * 16,
                     P[p] + (size_t)row * K + u * 32 + c * 8);
        }
        cp_commit();
    };

    int S = K >> 5;
    load_stage(0, 0);
    load_stage(1, 1);

    for (int s = 0; s < S; s++) {
        int b = s & 1;
        if (s + 1 < S) cp_wait<1>(); else cp_wait<0>();
        __syncthreads();
        unsigned base = smb + b * DBUF;
        #pragma unroll
        for (int ko = 0; ko < 2; ko++) {
            unsigned Af[2][4][4], Bf[2][4][4];
            #pragma unroll
            for (int mt = 0; mt < 4; mt++) {
                ldsm4(Af[0][mt], base + aBase + mt * 16 * DPIT + ko * 32);
                if (aLo)
                    ldsm4(Af[1][mt], base + DPLANE + aBase + mt * 16 * DPIT + ko * 32);
            }
            #pragma unroll
            for (int np = 0; np < 4; np++) {
                ldsm4(Bf[0][np], base + bBase + np * 16 * DPIT + ko * 32);
                if (bLo)
                    ldsm4(Bf[1][np], base + DPLANE + bBase + np * 16 * DPIT + ko * 32);
            }
            if (aLo) {
                #pragma unroll
                for (int nt = 0; nt < 8; nt++)
                    #pragma unroll
                    for (int mt = 0; mt < 4; mt++)
                        hmma(acc[mt][nt], Af[1][mt], &Bf[0][nt >> 1][(nt & 1) * 2]);
            }
            if (bLo) {
                #pragma unroll
                for (int nt = 0; nt < 8; nt++)
                    #pragma unroll
                    for (int mt = 0; mt < 4; mt++)
                        hmma(acc[mt][nt], Af[0][mt], &Bf[1][nt >> 1][(nt & 1) * 2]);
            }
            #pragma unroll
            for (int nt = 0; nt < 8; nt++)
                #pragma unroll
                for (int mt = 0; mt < 4; mt++)
                    hmma(acc[mt][nt], Af[0][mt], &Bf[0][nt >> 1][(nt & 1) * 2]);
        }
        __syncthreads();
        if (s + 2 < S) load_stage(s + 2, b);
    }

    #pragma unroll
    for (int mt = 0; mt < 4; mt++) {
        int r0 = bm + wm * 64 + mt * 16 + g;
        int r1 = r0 + 8;
        #pragma unroll
        for (int nt = 0; nt < 8; nt++) {
            int cn = bn + wn * 64 + nt * 8 + 2 * tig;
            float2 bv = *(const float2*)&bias[cn];
            float o0 = lrelu(acc[mt][nt][0] + bv.x);
            float o1 = lrelu(acc[mt][nt][1] + bv.y);
            float o2 = lrelu(acc[mt][nt][2] + bv.x);
            float o3 = lrelu(acc[mt][nt][3] + bv.y);
            if (Cf) {
                *(float2*)&Cf[(size_t)r0 * N + cn] = make_float2(o0, o1);
                *(float2*)&Cf[(size_t)r1 * N + cn] = make_float2(o2, o3);
            }
            if (Ch) {
                __half h0, l0, h1, l1, h2v, l2v, h3, l3;
                f16split(o0, h0, l0); f16split(o1, h1, l1);
                f16split(o2, h2v, l2v); f16split(o3, h3, l3);
                *(__half2*)&Ch[(size_t)r0 * N + cn] = __halves2half2(h0, h1);
                *(__half2*)&Ch[(size_t)r1 * N + cn] = __halves2half2(h2v, h3);
                if (Cl) {
                    *(__half2*)&Cl[(size_t)r0 * N + cn] = __halves2half2(l0, l1);
                    *(__half2*)&Cl[(size_t)r1 * N + cn] = __halves2half2(l2v, l3);
                }
            }
        }
    }
}

// ---------------------------------------------------------------------------
// Split-K HMMA (Wd3): Bl null -> 1-pass. Raw fp32 partials.
// ---------------------------------------------------------------------------
__global__ __launch_bounds__(128, 2) void hmma_partial(
    const __half* __restrict__ Ah,
    const __half* __restrict__ Bh, const __half* __restrict__ Bl,
    float* __restrict__ Cp, int M, int N, int K, int KC)
{
    extern __shared__ char dsm[];
    unsigned smb = sm_u32(dsm);
    int tid = threadIdx.x, lane = tid & 31, wid = tid >> 5;
    int wm = wid >> 1, wn = wid & 1, g = lane >> 2, tig = lane & 3;
    int bm = blockIdx.y * 128, bn = blockIdx.x * 128;
    int kOff = blockIdx.z * KC;
    bool bLo = (Bl != nullptr);

    const __half* P[4] = { Ah + (size_t)bm * K + kOff, nullptr,
                           Bh + (size_t)bn * K + kOff, bLo ? Bl + (size_t)bn * K + kOff : nullptr };

    float acc[4][8][4];
    #pragma unroll
    for (int i = 0; i < 4; i++)
        #pragma unroll
        for (int j = 0; j < 8; j++)
            #pragma unroll
            for (int q = 0; q < 4; q++) acc[i][j][q] = 0.f;

    unsigned aBase = (wm * 64 + (lane & 15)) * DPIT + ((lane >> 4) & 1) * 16;
    unsigned bBase = 2 * DPLANE + (wn * 64 + ((lane >> 4) & 1) * 8 + (lane & 7)) * DPIT
                     + ((lane >> 3) & 1) * 16;

    auto load_stage = [&](int u, int b) {
        #pragma unroll
        for (int i = 0; i < 16; i++) {
            int cid = i * 128 + tid;
            int p = cid >> 9, rem = cid & 511, row = rem >> 2, c = rem & 3;
            if (P[p])
                cp16(smb + b * DBUF + p * DPLANE + row * DPIT + c * 16,
                     P[p] + (size_t)row * K + u * 32 + c * 8);
        }
        cp_commit();
    };

    int S = KC >> 5;
    load_stage(0, 0);
    load_stage(1, 1);

    for (int s = 0; s < S; s++) {
        int b = s & 1;
        if (s + 1 < S) cp_wait<1>(); else cp_wait<0>();
        __syncthreads();
        unsigned base = smb + b * DBUF;
        #pragma unroll
        for (int ko = 0; ko < 2; ko++) {
            unsigned Af[4][4], Bf[2][4][4];
            #pragma unroll
            for (int mt = 0; mt < 4; mt++)
                ldsm4(Af[mt], base + aBase + mt * 16 * DPIT + ko * 32);
            #pragma unroll
            for (int np = 0; np < 4; np++) {
                ldsm4(Bf[0][np], base + bBase + np * 16 * DPIT + ko * 32);
                if (bLo)
                    ldsm4(Bf[1][np], base + DPLANE + bBase + np * 16 * DPIT + ko * 32);
            }
            if (bLo) {
                #pragma unroll
                for (int nt = 0; nt < 8; nt++)
                    #pragma unroll
                    for (int mt = 0; mt < 4; mt++)
                        hmma(acc[mt][nt], Af[mt], &Bf[1][nt >> 1][(nt & 1) * 2]);
            }
            #pragma unroll
            for (int nt = 0; nt < 8; nt++)
                #pragma unroll
                for (int mt = 0; mt < 4; mt++)
                    hmma(acc[mt][nt], Af[mt], &Bf[0][nt >> 1][(nt & 1) * 2]);
        }
        __syncthreads();
        if (s + 2 < S) load_stage(s + 2, b);
    }

    size_t zbase = (size_t)blockIdx.z * M * N;
    #pragma unroll
    for (int mt = 0; mt < 4; mt++) {
        int r0 = bm + wm * 64 + mt * 16 + g;
        int r1 = r0 + 8;
        #pragma unroll
        for (int nt = 0; nt < 8; nt++) {
            int cn = bn + wn * 64 + nt * 8 + 2 * tig;
            *(float2*)&Cp[zbase + (size_t)r0 * N + cn] = make_float2(acc[mt][nt][0], acc[mt][nt][1]);
            *(float2*)&Cp[zbase + (size_t)r1 * N + cn] = make_float2(acc[mt][nt][2], acc[mt][nt][3]);
        }
    }
}

__global__ void reduceK_kernel(const float* __restrict__ Cp, const float* __restrict__ bias,
                               float* __restrict__ X, int MN, int N, int Z) {
    int i4 = blockIdx.x * 256 + threadIdx.x;
    int n4 = MN >> 2;
    if (i4 >= n4) return;
    const float4* C4 = (const float4*)Cp;
    float4 s = C4[i4];
    for (int z = 1; z < Z; z++) {
        float4 v = C4[(size_t)z * n4 + i4];
        s.x += v.x; s.y += v.y; s.z += v.z; s.w += v.w;
    }
    int col = (i4 * 4) & (N - 1);
    float4 bv = *(const float4*)&bias[col];
    float4 o;
    o.x = lrelu(s.x + bv.x); o.y = lrelu(s.y + bv.y);
    o.z = lrelu(s.z + bv.z); o.w = lrelu(s.w + bv.w);
    ((float4*)X)[i4] = o;
}

// ---------------------------------------------------------------------------
// 2-pass screened VQ: d_hat = ||c||^2 - 2*xh.(ch+cl); exact-argmin guaranteed
// via per-thread top-3 + rigorous window (E = 2*||xl||*max||c||) + exact fp32
// recheck of in-window candidates; flagged rows (coverage uncertain) do a
// cooperative exact full scan.
// ---------------------------------------------------------------------------
#define BPLANE 20480
#define VBOFF  40960                      // A: 4 hi planes
#define VSMEM  (VBOFF + 2 * 2 * BPLANE)   // 122880

__global__ __launch_bounds__(256, 1) void hmma_vq(
    const __half* __restrict__ Ah, const __half* __restrict__ Al,
    const __half* __restrict__ cbh, const __half* __restrict__ cbl,
    const float* __restrict__ cbn, const float* __restrict__ cbf,
    const float* __restrict__ xf,
    float* __restrict__ quant, float* __restrict__ disc,
    __half* __restrict__ qh)
{
    extern __shared__ char dsm[];
    unsigned smb = sm_u32(dsm);
    __shared__ float sv[128][48];
    __shared__ int   si[128][48];
    __shared__ int   srow[128];
    __shared__ int   flist[128];
    __shared__ int   nflag;
    __shared__ float rv[256];
    __shared__ int   ri[256];
    int tid = threadIdx.x, lane = tid & 31, wid = tid >> 5;
    int wm = wid >> 2, wn = wid & 3, g = lane >> 2, tig = lane & 3;
    long bm = (long)blockIdx.x * 128;
    if (tid == 0) nflag = 0;

    float acc[4][8][4];
    #pragma unroll
    for (int i = 0; i < 4; i++)
        #pragma unroll
        for (int j = 0; j < 8; j++)
            #pragma unroll
            for (int q = 0; q < 4; q++) acc[i][j][q] = 0.f;

    float b_[8][3];
    int   i_[8][3];
    #pragma unroll
    for (int i = 0; i < 8; i++)
        #pragma unroll
        for (int k = 0; k < 3; k++) { b_[i][k] = 3.4e38f; i_[i][k] = 0x7fffffff; }

    unsigned aBase = (wm * 64 + (lane & 15)) * DPIT + ((lane >> 4) & 1) * 16;
    unsigned bBase = (wn * 64 + ((lane >> 4) & 1) * 8 + (lane & 7)) * DPIT
                     + ((lane >> 3) & 1) * 16;

    // A resident: 4 planes = Ah k-chunks
    #pragma unroll
    for (int i = 0; i < 8; i++) {
        int cid = i * 256 + tid;
        int p = cid >> 9, rem = cid & 511, row = rem >> 2, c = rem & 3;
        cp16(smb + p * DPLANE + row * DPIT + c * 16,
             Ah + (bm + row) * 128 + p * 32 + c * 8);
    }
    cp_commit();

    auto loadB = [&](int u, int b) {
        int slab = u >> 2, kc = u & 3;
        #pragma unroll
        for (int i = 0; i < 8; i++) {
            int cid = i * 256 + tid;
            int pl = cid >> 10, rem = cid & 1023, row = rem >> 2, c = rem & 3;
            const __half* base = pl ? cbl : cbh;
            cp16(smb + VBOFF + b * (2 * BPLANE) + pl * BPLANE + row * DPIT + c * 16,
                 base + (size_t)(slab * 256 + row) * 128 + kc * 32 + c * 8);
        }
        cp_commit();
    };
    loadB(0, 0);
    loadB(1, 1);

    for (int u = 0; u < 32; u++) {
        int b = u & 1, kc = u & 3;
        if (u + 1 < 32) cp_wait<1>(); else cp_wait<0>();
        __syncthreads();
        unsigned abase = smb + kc * DPLANE;
        unsigned bbase = smb + VBOFF + b * (2 * BPLANE);
        #pragma unroll
        for (int ko = 0; ko < 2; ko++) {
            unsigned Af[4][4], Bf[2][4][4];
            #pragma unroll
            for (int mt = 0; mt < 4; mt++)
                ldsm4(Af[mt], abase + aBase + mt * 16 * DPIT + ko * 32);
            #pragma unroll
            for (int np = 0; np < 4; np++) {
                ldsm4(Bf[0][np], bbase + bBase + np * 16 * DPIT + ko * 32);
                ldsm4(Bf[1][np], bbase + BPLANE + bBase + np * 16 * DPIT + ko * 32);
            }
            #pragma unroll
            for (int nt = 0; nt < 8; nt++)
                #pragma unroll
                for (int mt = 0; mt < 4; mt++)
                    hmma(acc[mt][nt], Af[mt], &Bf[1][nt >> 1][(nt & 1) * 2]);
            #pragma unroll
            for (int nt = 0; nt < 8; nt++)
                #pragma unroll
                for (int mt = 0; mt < 4; mt++)
                    hmma(acc[mt][nt], Af[mt], &Bf[0][nt >> 1][(nt & 1) * 2]);
        }
        if (kc == 3) {
            int c0 = (u >> 2) * 256;
            #pragma unroll
            for (int mt = 0; mt < 4; mt++) {
                #pragma unroll
                for (int nt = 0; nt < 8; nt++) {
                    int cn = c0 + wn * 64 + nt * 8 + 2 * tig;
                    float2 nn = *(const float2*)&cbn[cn];
                    float* a = acc[mt][nt];
                    ins3(b_[mt * 2], i_[mt * 2], nn.x - 2.f * a[0], cn);
                    ins3(b_[mt * 2], i_[mt * 2], nn.y - 2.f * a[1], cn + 1);
                    ins3(b_[mt * 2 + 1], i_[mt * 2 + 1], nn.x - 2.f * a[2], cn);
                    ins3(b_[mt * 2 + 1], i_[mt * 2 + 1], nn.y - 2.f * a[3], cn + 1);
                    a[0] = a[1] = a[2] = a[3] = 0.f;
                }
            }
        }
        __syncthreads();
        if (u + 2 < 32) loadB(u + 2, b);
    }

    #pragma unroll
    for (int mt = 0; mt < 4; mt++) {
        int r0 = wm * 64 + mt * 16 + g;
        int c3 = (wn * 4 + tig) * 3;
        #pragma unroll
        for (int k = 0; k < 3; k++) {
            sv[r0][c3 + k] = b_[mt * 2][k];         si[r0][c3 + k] = i_[mt * 2][k];
            sv[r0 + 8][c3 + k] = b_[mt * 2 + 1][k]; si[r0 + 8][c3 + k] = i_[mt * 2 + 1][k];
        }
    }
    __syncthreads();

    // per-row screening + exact recheck (one thread per row)
    if (tid < 128) {
        int row = tid;
        float dmin = 3.4e38f;
        #pragma unroll 8
        for (int k = 0; k < 48; k++) dmin = fminf(dmin, sv[row][k]);
        // ||xl|| from lo plane
        const __half2* xl2 = (const __half2*)(Al + (bm + row) * 128);
        float xs = 0.f;
        #pragma unroll 8
        for (int i = 0; i < 64; i++) {
            float2 v = __half22float2(xl2[i]);
            xs += v.x * v.x + v.y * v.y;
        }
        float maxC = sqrtf(__int_as_float(g_maxnI));
        float E = 2.f * sqrtf(xs) * maxC * 1.05f + 1e-3f;
        float thresh = dmin + 2.f * E;
        bool flag = false;
        #pragma unroll 4
        for (int g16 = 0; g16 < 16; g16++)
            if (sv[row][g16 * 3 + 2] <= thresh) flag = true;
        if (flag) {
            int p = atomicAdd(&nflag, 1);
            flist[p] = row;
        } else {
            float bd = 3.4e38f; int bi = 0x7fffffff;
            const float4* xr = (const float4*)(xf + (bm + row) * 128);
            for (int k = 0; k < 48; k++) {
                if (sv[row][k] <= thresh) {
                    int c = si[row][k];
                    const float4* cr = (const float4*)(cbf + (size_t)c * 128);
                    float s = 0.f;
                    #pragma unroll 8
                    for (int i = 0; i < 32; i++) {
                        float4 a4 = xr[i], c4 = cr[i];
                        s += a4.x * c4.x + a4.y * c4.y + a4.z * c4.z + a4.w * c4.w;
                    }
                    float de = cbn[c] - 2.f * s;
                    if (de < bd || (de == bd && c < bi)) { bd = de; bi = c; }
                }
            }
            srow[row] = bi;
        }
    }
    __syncthreads();

    // fallback: exact full scan for flagged rows (expected never)
    for (int j = 0; j < nflag; j++) {
        int row = flist[j];
        float bd = 3.4e38f; int bi = 0x7fffffff;
        const float4* xr = (const float4*)(xf + (bm + row) * 128);
        for (int c = tid * 8; c < tid * 8 + 8; c++) {
            const float4* cr = (const float4*)(cbf + (size_t)c * 128);
            float s = 0.f;
            #pragma unroll 8
            for (int i = 0; i < 32; i++) {
                float4 a4 = xr[i], c4 = cr[i];
                s += a4.x * c4.x + a4.y * c4.y + a4.z * c4.z + a4.w * c4.w;
            }
            float de = cbn[c] - 2.f * s;
            if (de < bd || (de == bd && c < bi)) { bd = de; bi = c; }
        }
        rv[tid] = bd; ri[tid] = bi;
        __syncthreads();
        if (tid == 0) {
            float v = rv[0]; int x = ri[0];
            for (int t = 1; t < 256; t++)
                if (rv[t] < v || (rv[t] == v && ri[t] < x)) { v = rv[t]; x = ri[t]; }
            srow[row] = x;
        }
        __syncthreads();
    }

    // outputs
    for (int it = tid; it < 128 * 512; it += 256) {
        int rr = it >> 9, c4 = it & 511;
        float4 z = make_float4(0.f, 0.f, 0.f, 0.f);
        int bi = srow[rr];
        if ((bi >> 2) == c4) ((float*)&z)[bi & 3] = 1.0f;
        ((float4*)disc)[(bm + rr) * 512 + c4] = z;
    }
    for (int it = tid; it < 128 * 32; it += 256) {
        int rr = it >> 5, c = it & 31;
        ((float4*)quant)[(bm + rr) * 32 + c] = ((const float4*)cbf)[srow[rr] * 32 + c];
    }
    for (int it = tid; it < 128 * 16; it += 256) {
        int rr = it >> 4, c = it & 15;
        ((uint4*)qh)[(bm + rr) * 16 + c] = ((const uint4*)cbh)[srow[rr] * 16 + c];
    }
}

// ---------------------------------------------------------------------------
// FFMA skinny layers (32x128 tile), exact fp32, optional fp16 hi/lo epilogue
// ---------------------------------------------------------------------------
__global__ __launch_bounds__(256) void dense_lrelu_32(
    const float* __restrict__ A, const float* __restrict__ W,
    const float* __restrict__ bias, float* __restrict__ C,
    __half* __restrict__ Chi, __half* __restrict__ Clo,
    int M, int N, int K)
{
    __shared__ float As[2][8][32];
    __shared__ float Bs[2][8][128];
    int tid = threadIdx.x, tx = tid & 15, ty = tid >> 4;
    int bm = blockIdx.y * 32, bn = blockIdx.x * 128;
    int arow = tid >> 3, acol = tid & 7;
    int wrow = tid >> 5, wcol = (tid & 31) * 4;

    unsigned long long acc[2][4];
    #pragma unroll
    for (int i = 0; i < 2; i++)
        #pragma unroll
        for (int j = 0; j < 4; j++) acc[i][j] = 0ULL;

    const float* Ap = A + (size_t)(bm + arow) * K + acol;
    const float* Wp = W + (size_t)wrow * N + bn + wcol;
    size_t wstep = (size_t)8 * N;
    int T = K >> 3;
    float areg = *Ap;  Ap += 8;
    cp16(sm_u32(&Bs[0][wrow][wcol]), Wp); Wp += wstep;
    cp_commit();

    for (int i = 0; i < T; i++) {
        int cur = i & 1;
        As[cur][acol][arow] = areg;
        if (i + 1 < T) {
            areg = *Ap;  Ap += 8;
            cp16(sm_u32(&Bs[cur ^ 1][wrow][wcol]), Wp); Wp += wstep;
            cp_commit();
            cp_wait<1>();
        } else cp_wait<0>();
        __syncthreads();
        #pragma unroll
        for (int kk = 0; kk < 8; kk++) {
            float2 a2 = *(const float2*)&As[cur][kk][ty * 2];
            float4 b0 = *(const float4*)&Bs[cur][kk][tx * 4];
            float4 b1 = *(const float4*)&Bs[cur][kk][64 + tx * 4];
            unsigned long long bp[4] = { pack2(b0.x, b0.y), pack2(b0.z, b0.w),
                                         pack2(b1.x, b1.y), pack2(b1.z, b1.w) };
            unsigned long long a0 = pack2(a2.x, a2.x), a1 = pack2(a2.y, a2.y);
            fma2(acc[0][0], a0, bp[0]); fma2(acc[0][1], a0, bp[1]);
            fma2(acc[0][2], a0, bp[2]); fma2(acc[0][3], a0, bp[3]);
            fma2(acc[1][0], a1, bp[0]); fma2(acc[1][1], a1, bp[1]);
            fma2(acc[1][2], a1, bp[2]); fma2(acc[1][3], a1, bp[3]);
        }
        __syncthreads();
    }

    float bb0[4], bb1[4];
    #pragma unroll
    for (int j = 0; j < 4; j++) {
        bb0[j] = __ldg(&bias[bn + tx * 4 + j]);
        bb1[j] = __ldg(&bias[bn + 64 + tx * 4 + j]);
    }
    #pragma unroll
    for (int i = 0; i < 2; i++) {
        int r = bm + ty * 2 + i;
        float2 p0 = unpack2(acc[i][0]), p1 = unpack2(acc[i][1]);
        float2 p2 = unpack2(acc[i][2]), p3 = unpack2(acc[i][3]);
        float o[8];
        o[0] = lrelu(p0.x + bb0[0]); o[1] = lrelu(p0.y + bb0[1]);
        o[2] = lrelu(p1.x + bb0[2]); o[3] = lrelu(p1.y + bb0[3]);
        o[4] = lrelu(p2.x + bb1[0]); o[5] = lrelu(p2.y + bb1[1]);
        o[6] = lrelu(p3.x + bb1[2]); o[7] = lrelu(p3.y + bb1[3]);
        *(float4*)&C[(size_t)r * N + bn + tx * 4]      = make_float4(o[0], o[1], o[2], o[3]);
        *(float4*)&C[(size_t)r * N + bn + 64 + tx * 4] = make_float4(o[4], o[5], o[6], o[7]);
        if (Chi) {
            #pragma unroll
            for (int j = 0; j < 8; j++) {
                int cc = bn + ((j < 4) ? 0 : 64) + tx * 4 + (j & 3);
                __half h, l; f16split(o[j], h, l);
                Chi[(size_t)r * N + cc] = h;
                Clo[(size_t)r * N + cc] = l;
            }
        }
    }
}

// ---------------------------------------------------------------------------
extern "C" void kernel_launch(void* const* d_in, const int* in_sizes, int n_in,
                              void* d_out, int out_size) {
    const float* cond = (const float*)d_in[0];
    const float* cb   = (const float*)d_in[1];
    const float* We1  = (const float*)d_in[2];  const float* be1 = (const float*)d_in[3];
    const float* We2  = (const float*)d_in[4];  const float* be2 = (const float*)d_in[5];
    const float* We3  = (const float*)d_in[6];  const float* be3 = (const float*)d_in[7];
    const float* We4  = (const float*)d_in[8];  const float* be4 = (const float*)d_in[9];
    const float* Wd1  = (const float*)d_in[10]; const float* bd1 = (const float*)d_in[11];
    const float* Wd2  = (const float*)d_in[12]; const float* bd2 = (const float*)d_in[13];
    const float* Wd3  = (const float*)d_in[14]; const float* bd3 = (const float*)d_in[15];
    const float* Wd4  = (const float*)d_in[16]; const float* bd4 = (const float*)d_in[17];

    float* out   = (float*)d_out;
    float* recon = out;
    float* enc   = recon + (size_t)BQ * 256;
    float* disc  = enc   + (size_t)BQ * LE;
    float* quant = disc  + (size_t)NROWS * KCB;

    float *x1, *bf, *cbn;
    __half *x1h, *x1l, *h1, *l1, *h2, *l2;
    __half *w2h, *w2l, *w3h, *w3l, *w4h, *w4l, *d1h, *d1l, *d2h, *d2l, *d3h, *d3l, *cbh, *cbl;
    cudaGetSymbolAddress((void**)&x1,  g_x1);  cudaGetSymbolAddress((void**)&bf,  g_bf);
    cudaGetSymbolAddress((void**)&x1h, g_x1h); cudaGetSymbolAddress((void**)&x1l, g_x1l);
    cudaGetSymbolAddress((void**)&h1,  g_h1);  cudaGetSymbolAddress((void**)&l1,  g_l1);
    cudaGetSymbolAddress((void**)&h2,  g_h2);  cudaGetSymbolAddress((void**)&l2,  g_l2);
    cudaGetSymbolAddress((void**)&w2h, g_w2h); cudaGetSymbolAddress((void**)&w2l, g_w2l);
    cudaGetSymbolAddress((void**)&w3h, g_w3h); cudaGetSymbolAddress((void**)&w3l, g_w3l);
    cudaGetSymbolAddress((void**)&w4h, g_w4h); cudaGetSymbolAddress((void**)&w4l, g_w4l);
    cudaGetSymbolAddress((void**)&d1h, g_d1h); cudaGetSymbolAddress((void**)&d1l, g_d1l);
    cudaGetSymbolAddress((void**)&d2h, g_d2h); cudaGetSymbolAddress((void**)&d2l, g_d2l);
    cudaGetSymbolAddress((void**)&d3h, g_d3h); cudaGetSymbolAddress((void**)&d3l, g_d3l);
    cudaGetSymbolAddress((void**)&cbh, g_cbh); cudaGetSymbolAddress((void**)&cbl, g_cbl);
    cudaGetSymbolAddress((void**)&cbn, g_cbn);

    cudaFuncSetAttribute(hmma_dense,   cudaFuncAttributeMaxDynamicSharedMemorySize, DSMEM);
    cudaFuncSetAttribute(hmma_partial, cudaFuncAttributeMaxDynamicSharedMemorySize, DSMEM);
    cudaFuncSetAttribute(hmma_vq,      cudaFuncAttributeMaxDynamicSharedMemorySize, VSMEM);

    wtsplit_kernel<<<dim3(64, 2),  256>>>(We2, w2h, w2l, EE, LE);                       // 0
    dense_lrelu_32<<<dim3(1, 128), 256>>>(cond, We1, be1, x1, x1h, x1l, BQ, EE, 256);   // 1
    wtsplit_kernel<<<dim3(64, 32), 256>>>(We3, w3h, w3l, LE, LE);                       // 2
    hmma_dense<<<dim3(16, 32), 128, DSMEM>>>(x1h, x1l, w2h, w2l, be2, nullptr, h1, l1, BQ, LE, EE);  // 3 (profiled)
    hmma_dense<<<dim3(16, 32), 128, DSMEM>>>(h1, l1, w3h, w3l, be3, nullptr, h2, l2, BQ, LE, LE);    // 4
    wtsplit_kernel<<<dim3(64, 32), 256>>>(We4, w4h, w4l, LE, LE);                       // 5
    hmma_dense<<<dim3(16, 32), 128, DSMEM>>>(h2, l2, w4h, w4l, be4, enc, h1, l1, BQ, LE, LE);        // 6
    cbsplit_kernel<<<KCB, 128>>>(cb, cbh, cbl, cbn);                                    // 7
    wtsplit_kernel<<<dim3(64, 32), 256>>>(Wd1, d1h, d1l, LE, LE);                       // 8
    wtsplit_kernel<<<dim3(64, 32), 256>>>(Wd2, d2h, d2l, LE, LE);                       // 9
    wtsplit_kernel<<<dim3(4, 32),  256>>>(Wd3, d3h, d3l, LE, EE);                       // 10
    // VQ: 2-pass screened, exact argmin guaranteed
    hmma_vq<<<NROWS / 128, 256, VSMEM>>>(h1, l1, cbh, cbl, cbn, cb, enc, quant, disc, h2); // 11
    // decoder: Wd1 1-pass, Wd2 1-pass, Wd3 split-K 1-pass, Wd4 exact FFMA
    hmma_dense<<<dim3(16, 32), 128, DSMEM>>>(h2, nullptr, d1h, nullptr, bd1, nullptr, h1, nullptr, BQ, LE, LE); // 12
    hmma_dense<<<dim3(16, 32), 128, DSMEM>>>(h1, nullptr, d2h, nullptr, bd2, nullptr, h2, nullptr, BQ, LE, LE); // 13
    hmma_partial<<<dim3(1, 32, 8), 128, DSMEM>>>(h2, d3h, nullptr, bf, BQ, EE, LE, 256); // 14
    reduceK_kernel<<<(BQ * EE / 4 + 255) / 256, 256>>>(bf, bd3, x1, BQ * EE, EE, 8);    // 15
    dense_lrelu_32<<<dim3(2, 128), 256>>>(x1, Wd4, bd4, recon, nullptr, nullptr, BQ, 256, EE); // 16
}

// round 14
// speedup vs baseline: 1.0257x; 1.0257x over previous
#include <cuda_runtime.h>
#include <cuda_fp16.h>

#define BQ 4096
#define LE 2048
#define EE 128
#define KCB 2048
#define NROWS 65536

// ---- scratch ---------------------------------------------------------------
__device__ float  g_x1 [BQ * EE];
__device__ __half g_x1h[BQ * EE];
__device__ __half g_x1l[BQ * EE];
__device__ float  g_bf [BQ * LE];          // split-K partial scratch
__device__ __half g_h1 [BQ * LE];
__device__ __half g_l1 [BQ * LE];
__device__ __half g_h2 [BQ * LE];
__device__ __half g_l2 [BQ * LE];
__device__ __half g_w2h[LE * EE],  g_w2l[LE * EE];
__device__ __half g_w3h[LE * LE],  g_w3l[LE * LE];
__device__ __half g_w4h[LE * LE],  g_w4l[LE * LE];
__device__ __half g_d1h[LE * LE],  g_d1l[LE * LE];
__device__ __half g_d2h[LE * LE],  g_d2l[LE * LE];
__device__ __half g_d3h[EE * LE],  g_d3l[EE * LE];
__device__ __half g_cbh[KCB * EE], g_cbl[KCB * EE];
__device__ float  g_cbn[KCB];
__device__ float  g_xln[NROWS];            // per-row ||x_lo||
__device__ int    g_maxnI;                 // max ||c||^2 (bits of positive float)

__device__ __forceinline__ float lrelu(float v) { return fmaxf(v, 0.2f * v); }

__device__ __forceinline__ void f16split(float x, __half& h, __half& l) {
    h = __float2half_rn(x);
    l = __float2half_rn(x - __half2float(h));
}
__device__ __forceinline__ unsigned sm_u32(const void* p) {
    return (unsigned)__cvta_generic_to_shared(p);
}
__device__ __forceinline__ void cp16(unsigned s, const void* g) {
    asm volatile("cp.async.cg.shared.global [%0], [%1], 16;" :: "r"(s), "l"(g));
}
__device__ __forceinline__ void cp_commit() { asm volatile("cp.async.commit_group;"); }
template<int N> __device__ __forceinline__ void cp_wait() {
    asm volatile("cp.async.wait_group %0;" :: "n"(N));
}
__device__ __forceinline__ void hmma(float* c, const unsigned* a, const unsigned* b) {
    asm volatile(
        "mma.sync.aligned.m16n8k16.row.col.f32.f16.f16.f32 "
        "{%0,%1,%2,%3}, {%4,%5,%6,%7}, {%8,%9}, {%0,%1,%2,%3};"
        : "+f"(c[0]), "+f"(c[1]), "+f"(c[2]), "+f"(c[3])
        : "r"(a[0]), "r"(a[1]), "r"(a[2]), "r"(a[3]), "r"(b[0]), "r"(b[1]));
}
__device__ __forceinline__ void ldsm4(unsigned* r, unsigned addr) {
    asm volatile("ldmatrix.sync.aligned.m8n8.x4.shared.b16 {%0,%1,%2,%3}, [%4];"
        : "=r"(r[0]), "=r"(r[1]), "=r"(r[2]), "=r"(r[3]) : "r"(addr));
}
// top-3 sorted insert (strict <, ascending-index arrival preserves first-index ties)
__device__ __forceinline__ void ins3(float* b, int* ix, float d, int c) {
    if (d < b[2]) {
        if (d < b[1]) {
            b[2] = b[1]; ix[2] = ix[1];
            if (d < b[0]) { b[1] = b[0]; ix[1] = ix[0]; b[0] = d; ix[0] = c; }
            else { b[1] = d; ix[1] = c; }
        } else { b[2] = d; ix[2] = c; }
    }
}
// ---- packed fp32x2 (skinny FFMA path) --------------------------------------
__device__ __forceinline__ unsigned long long pack2(float lo, float hi) {
    unsigned long long r;
    asm("mov.b64 %0, {%1, %2};" : "=l"(r) : "f"(lo), "f"(hi));
    return r;
}
__device__ __forceinline__ void fma2(unsigned long long& a,
                                     unsigned long long x, unsigned long long y) {
    asm("fma.rn.f32x2 %0, %1, %2, %0;" : "+l"(a) : "l"(x), "l"(y));
}
__device__ __forceinline__ float2 unpack2(unsigned long long v) {
    float lo, hi;
    asm("mov.b64 {%0, %1}, %2;" : "=f"(lo), "=f"(hi) : "l"(v));
    return make_float2(lo, hi);
}

// ---------------------------------------------------------------------------
// prep
// ---------------------------------------------------------------------------
__global__ void wtsplit_kernel(const float* __restrict__ W, __half* __restrict__ Th,
                               __half* __restrict__ Tl, int K, int N) {
    __shared__ float t[64][33];
    int n0 = blockIdx.x * 32, k0 = blockIdx.y * 64;
    int tx = threadIdx.x & 31, tr = threadIdx.x >> 5;
    for (int r = tr; r < 64; r += 8) t[r][tx] = W[(size_t)(k0 + r) * N + n0 + tx];
    __syncthreads();
    for (int r2 = tr; r2 < 32; r2 += 8) {
        __half h0, l0, h1, l1;
        f16split(t[2 * tx][r2], h0, l0);
        f16split(t[2 * tx + 1][r2], h1, l1);
        *(__half2*)&Th[(size_t)(n0 + r2) * K + k0 + 2 * tx] = __halves2half2(h0, h1);
        *(__half2*)&Tl[(size_t)(n0 + r2) * K + k0 + 2 * tx] = __halves2half2(l0, l1);
    }
}
__global__ void cbsplit_kernel(const float* __restrict__ cb, __half* __restrict__ hi,
                               __half* __restrict__ lo, float* __restrict__ nrm) {
    int n = blockIdx.x, e = threadIdx.x;
    float v = cb[n * EE + e];
    __half h, l; f16split(v, h, l);
    hi[n * EE + e] = h;
    lo[n * EE + e] = l;
    float q = v * v;
    #pragma unroll
    for (int o = 16; o > 0; o >>= 1) q += __shfl_xor_sync(0xFFFFFFFFu, q, o);
    __shared__ float ws[4];
    if ((e & 31) == 0) ws[e >> 5] = q;
    __syncthreads();
    if (e == 0) {
        float nn = ws[0] + ws[1] + ws[2] + ws[3];
        nrm[n] = nn;
        atomicMax(&g_maxnI, __float_as_int(nn));
    }
}
// per-row ||x_lo|| (warp per row, coalesced)
__global__ void xln_kernel(const __half* __restrict__ L, float* __restrict__ xln) {
    int row = blockIdx.x * 8 + (threadIdx.x >> 5);
    int lane = threadIdx.x & 31;
    const __half2* p = (const __half2*)(L + (size_t)row * 128);
    float2 v0 = __half22float2(p[lane]);
    float2 v1 = __half22float2(p[lane + 32]);
    float s = v0.x * v0.x + v0.y * v0.y + v1.x * v1.x + v1.y * v1.y;
    #pragma unroll
    for (int o = 16; o > 0; o >>= 1) s += __shfl_xor_sync(0xFFFFFFFFu, s, o);
    if (lane == 0) xln[row] = sqrtf(s);
}

// ---------------------------------------------------------------------------
// FP16 dense: 128 threads, 4 warps (2x2 of 64x64), BK=32.
// ---------------------------------------------------------------------------
#define DPIT   80
#define DPLANE 10240
#define DBUF   40960
#define DSMEM  81920

__global__ __launch_bounds__(128, 2) void hmma_dense(
    const __half* __restrict__ Ah, const __half* __restrict__ Al,
    const __half* __restrict__ Bh, const __half* __restrict__ Bl,
    const float* __restrict__ bias,
    float* __restrict__ Cf, __half* __restrict__ Ch, __half* __restrict__ Cl,
    int M, int N, int K)
{
    extern __shared__ char dsm[];
    unsigned smb = sm_u32(dsm);
    int tid = threadIdx.x, lane = tid & 31, wid = tid >> 5;
    int wm = wid >> 1, wn = wid & 1, g = lane >> 2, tig = lane & 3;
    int bm = blockIdx.y * 128, bn = blockIdx.x * 128;
    bool aLo = (Al != nullptr), bLo = (Bl != nullptr);

    const __half* P[4] = { Ah + (size_t)bm * K, aLo ? Al + (size_t)bm * K : nullptr,
                           Bh + (size_t)bn * K, bLo ? Bl + (size_t)bn * K : nullptr };

    float acc[4][8][4];
    #pragma unroll
    for (int i = 0; i < 4; i++)
        #pragma unroll
        for (int j = 0; j < 8; j++)
            #pragma unroll
            for (int q = 0; q < 4; q++) acc[i][j][q] = 0.f;

    unsigned aBase = (wm * 64 + (lane & 15)) * DPIT + ((lane >> 4) & 1) * 16;
    unsigned bBase = 2 * DPLANE + (wn * 64 + ((lane >> 4) & 1) * 8 + (lane & 7)) * DPIT
                     + ((lane >> 3) & 1) * 16;

    auto load_stage = [&](int u, int b) {
        #pragma unroll
        for (int i = 0; i < 16; i++) {
            int cid = i * 128 + tid;
            int p = cid >> 9, rem = cid & 511, row = rem >> 2, c = rem & 3;
            if (P[p])
                cp16(smb + b * DBUF + p * DPLANE + row * DPIT + c * 16,
                     P[p] + (size_t)row * K + u * 32 + c * 8);
        }
        cp_commit();
    };

    int S = K >> 5;
    load_stage(0, 0);
    load_stage(1, 1);

    for (int s = 0; s < S; s++) {
        int b = s & 1;
        if (s + 1 < S) cp_wait<1>(); else cp_wait<0>();
        __syncthreads();
        unsigned base = smb + b * DBUF;
        #pragma unroll
        for (int ko = 0; ko < 2; ko++) {
            unsigned Af[2][4][4], Bf[2][4][4];
            #pragma unroll
            for (int mt = 0; mt < 4; mt++) {
                ldsm4(Af[0][mt], base + aBase + mt * 16 * DPIT + ko * 32);
                if (aLo)
                    ldsm4(Af[1][mt], base + DPLANE + aBase + mt * 16 * DPIT + ko * 32);
            }
            #pragma unroll
            for (int np = 0; np < 4; np++) {
                ldsm4(Bf[0][np], base + bBase + np * 16 * DPIT + ko * 32);
                if (bLo)
                    ldsm4(Bf[1][np], base + DPLANE + bBase + np * 16 * DPIT + ko * 32);
            }
            if (aLo) {
                #pragma unroll
                for (int nt = 0; nt < 8; nt++)
                    #pragma unroll
                    for (int mt = 0; mt < 4; mt++)
                        hmma(acc[mt][nt], Af[1][mt], &Bf[0][nt >> 1][(nt & 1) * 2]);
            }
            if (bLo) {
                #pragma unroll
                for (int nt = 0; nt < 8; nt++)
                    #pragma unroll
                    for (int mt = 0; mt < 4; mt++)
                        hmma(acc[mt][nt], Af[0][mt], &Bf[1][nt >> 1][(nt & 1) * 2]);
            }
            #pragma unroll
            for (int nt = 0; nt < 8; nt++)
                #pragma unroll
                for (int mt = 0; mt < 4; mt++)
                    hmma(acc[mt][nt], Af[0][mt], &Bf[0][nt >> 1][(nt & 1) * 2]);
        }
        __syncthreads();
        if (s + 2 < S) load_stage(s + 2, b);
    }

    #pragma unroll
    for (int mt = 0; mt < 4; mt++) {
        int r0 = bm + wm * 64 + mt * 16 + g;
        int r1 = r0 + 8;
        #pragma unroll
        for (int nt = 0; nt < 8; nt++) {
            int cn = bn + wn * 64 + nt * 8 + 2 * tig;
            float2 bv = *(const float2*)&bias[cn];
            float o0 = lrelu(acc[mt][nt][0] + bv.x);
            float o1 = lrelu(acc[mt][nt][1] + bv.y);
            float o2 = lrelu(acc[mt][nt][2] + bv.x);
            float o3 = lrelu(acc[mt][nt][3] + bv.y);
            if (Cf) {
                *(float2*)&Cf[(size_t)r0 * N + cn] = make_float2(o0, o1);
                *(float2*)&Cf[(size_t)r1 * N + cn] = make_float2(o2, o3);
            }
            if (Ch) {
                __half h0, l0, h1, l1, h2v, l2v, h3, l3;
                f16split(o0, h0, l0); f16split(o1, h1, l1);
                f16split(o2, h2v, l2v); f16split(o3, h3, l3);
                *(__half2*)&Ch[(size_t)r0 * N + cn] = __halves2half2(h0, h1);
                *(__half2*)&Ch[(size_t)r1 * N + cn] = __halves2half2(h2v, h3);
                if (Cl) {
                    *(__half2*)&Cl[(size_t)r0 * N + cn] = __halves2half2(l0, l1);
                    *(__half2*)&Cl[(size_t)r1 * N + cn] = __halves2half2(l2v, l3);
                }
            }
        }
    }
}

// ---------------------------------------------------------------------------
// Split-K HMMA (Wd3): Bl null -> 1-pass. Raw fp32 partials.
// ---------------------------------------------------------------------------
__global__ __launch_bounds__(128, 2) void hmma_partial(
    const __half* __restrict__ Ah,
    const __half* __restrict__ Bh, const __half* __restrict__ Bl,
    float* __restrict__ Cp, int M, int N, int K, int KC)
{
    extern __shared__ char dsm[];
    unsigned smb = sm_u32(dsm);
    int tid = threadIdx.x, lane = tid & 31, wid = tid >> 5;
    int wm = wid >> 1, wn = wid & 1, g = lane >> 2, tig = lane & 3;
    int bm = blockIdx.y * 128, bn = blockIdx.x * 128;
    int kOff = blockIdx.z * KC;
    bool bLo = (Bl != nullptr);

    const __half* P[4] = { Ah + (size_t)bm * K + kOff, nullptr,
                           Bh + (size_t)bn * K + kOff, bLo ? Bl + (size_t)bn * K + kOff : nullptr };

    float acc[4][8][4];
    #pragma unroll
    for (int i = 0; i < 4; i++)
        #pragma unroll
        for (int j = 0; j < 8; j++)
            #pragma unroll
            for (int q = 0; q < 4; q++) acc[i][j][q] = 0.f;

    unsigned aBase = (wm * 64 + (lane & 15)) * DPIT + ((lane >> 4) & 1) * 16;
    unsigned bBase = 2 * DPLANE + (wn * 64 + ((lane >> 4) & 1) * 8 + (lane & 7)) * DPIT
                     + ((lane >> 3) & 1) * 16;

    auto load_stage = [&](int u, int b) {
        #pragma unroll
        for (int i = 0; i < 16; i++) {
            int cid = i * 128 + tid;
            int p = cid >> 9, rem = cid & 511, row = rem >> 2, c = rem & 3;
            if (P[p])
                cp16(smb + b * DBUF + p * DPLANE + row * DPIT + c * 16,
                     P[p] + (size_t)row * K + u * 32 + c * 8);
        }
        cp_commit();
    };

    int S = KC >> 5;
    load_stage(0, 0);
    load_stage(1, 1);

    for (int s = 0; s < S; s++) {
        int b = s & 1;
        if (s + 1 < S) cp_wait<1>(); else cp_wait<0>();
        __syncthreads();
        unsigned base = smb + b * DBUF;
        #pragma unroll
        for (int ko = 0; ko < 2; ko++) {
            unsigned Af[4][4], Bf[2][4][4];
            #pragma unroll
            for (int mt = 0; mt < 4; mt++)
                ldsm4(Af[mt], base + aBase + mt * 16 * DPIT + ko * 32);
            #pragma unroll
            for (int np = 0; np < 4; np++) {
                ldsm4(Bf[0][np], base + bBase + np * 16 * DPIT + ko * 32);
                if (bLo)
                    ldsm4(Bf[1][np], base + DPLANE + bBase + np * 16 * DPIT + ko * 32);
            }
            if (bLo) {
                #pragma unroll
                for (int nt = 0; nt < 8; nt++)
                    #pragma unroll
                    for (int mt = 0; mt < 4; mt++)
                        hmma(acc[mt][nt], Af[mt], &Bf[1][nt >> 1][(nt & 1) * 2]);
            }
            #pragma unroll
            for (int nt = 0; nt < 8; nt++)
                #pragma unroll
                for (int mt = 0; mt < 4; mt++)
                    hmma(acc[mt][nt], Af[mt], &Bf[0][nt >> 1][(nt & 1) * 2]);
        }
        __syncthreads();
        if (s + 2 < S) load_stage(s + 2, b);
    }

    size_t zbase = (size_t)blockIdx.z * M * N;
    #pragma unroll
    for (int mt = 0; mt < 4; mt++) {
        int r0 = bm + wm * 64 + mt * 16 + g;
        int r1 = r0 + 8;
        #pragma unroll
        for (int nt = 0; nt < 8; nt++) {
            int cn = bn + wn * 64 + nt * 8 + 2 * tig;
            *(float2*)&Cp[zbase + (size_t)r0 * N + cn] = make_float2(acc[mt][nt][0], acc[mt][nt][1]);
            *(float2*)&Cp[zbase + (size_t)r1 * N + cn] = make_float2(acc[mt][nt][2], acc[mt][nt][3]);
        }
    }
}

__global__ void reduceK_kernel(const float* __restrict__ Cp, const float* __restrict__ bias,
                               float* __restrict__ X, int MN, int N, int Z) {
    int i4 = blockIdx.x * 256 + threadIdx.x;
    int n4 = MN >> 2;
    if (i4 >= n4) return;
    const float4* C4 = (const float4*)Cp;
    float4 s = C4[i4];
    for (int z = 1; z < Z; z++) {
        float4 v = C4[(size_t)z * n4 + i4];
        s.x += v.x; s.y += v.y; s.z += v.z; s.w += v.w;
    }
    int col = (i4 * 4) & (N - 1);
    float4 bv = *(const float4*)&bias[col];
    float4 o;
    o.x = lrelu(s.x + bv.x); o.y = lrelu(s.y + bv.y);
    o.z = lrelu(s.z + bv.z); o.w = lrelu(s.w + bv.w);
    ((float4*)X)[i4] = o;
}

// ---------------------------------------------------------------------------
// 2-pass screened VQ, warp-cooperative epilogue. Exact argmin guaranteed.
// ---------------------------------------------------------------------------
#define BPLANE 20480
#define VBOFF  40960                      // A: 4 hi planes
#define VSMEM  (VBOFF + 2 * 2 * BPLANE)   // 122880

__global__ __launch_bounds__(256, 1) void hmma_vq(
    const __half* __restrict__ Ah,
    const __half* __restrict__ cbh, const __half* __restrict__ cbl,
    const float* __restrict__ cbn, const float* __restrict__ cbf,
    const float* __restrict__ xf, const float* __restrict__ xln,
    float* __restrict__ quant, float* __restrict__ disc,
    __half* __restrict__ qh)
{
    extern __shared__ char dsm[];
    unsigned smb = sm_u32(dsm);
    __shared__ float sv[128][48];
    __shared__ int   si[128][48];
    __shared__ int   srow[128];
    __shared__ int   flist[128];
    __shared__ int   nflag;
    __shared__ float rv[256];
    __shared__ int   ri[256];
    __shared__ int   cand[8][16];
    __shared__ int   ncand[8];
    int tid = threadIdx.x, lane = tid & 31, wid = tid >> 5;
    int wm = wid >> 2, wn = wid & 3, g = lane >> 2, tig = lane & 3;
    long bm = (long)blockIdx.x * 128;
    if (tid == 0) nflag = 0;

    float acc[4][8][4];
    #pragma unroll
    for (int i = 0; i < 4; i++)
        #pragma unroll
        for (int j = 0; j < 8; j++)
            #pragma unroll
            for (int q = 0; q < 4; q++) acc[i][j][q] = 0.f;

    float b_[8][3];
    int   i_[8][3];
    #pragma unroll
    for (int i = 0; i < 8; i++)
        #pragma unroll
        for (int k = 0; k < 3; k++) { b_[i][k] = 3.4e38f; i_[i][k] = 0x7fffffff; }

    unsigned aBase = (wm * 64 + (lane & 15)) * DPIT + ((lane >> 4) & 1) * 16;
    unsigned bBase = (wn * 64 + ((lane >> 4) & 1) * 8 + (lane & 7)) * DPIT
                     + ((lane >> 3) & 1) * 16;

    #pragma unroll
    for (int i = 0; i < 8; i++) {
        int cid = i * 256 + tid;
        int p = cid >> 9, rem = cid & 511, row = rem >> 2, c = rem & 3;
        cp16(smb + p * DPLANE + row * DPIT + c * 16,
             Ah + (bm + row) * 128 + p * 32 + c * 8);
    }
    cp_commit();

    auto loadB = [&](int u, int b) {
        int slab = u >> 2, kc = u & 3;
        #pragma unroll
        for (int i = 0; i < 8; i++) {
            int cid = i * 256 + tid;
            int pl = cid >> 10, rem = cid & 1023, row = rem >> 2, c = rem & 3;
            const __half* base = pl ? cbl : cbh;
            cp16(smb + VBOFF + b * (2 * BPLANE) + pl * BPLANE + row * DPIT + c * 16,
                 base + (size_t)(slab * 256 + row) * 128 + kc * 32 + c * 8);
        }
        cp_commit();
    };
    loadB(0, 0);
    loadB(1, 1);

    for (int u = 0; u < 32; u++) {
        int b = u & 1, kc = u & 3;
        if (u + 1 < 32) cp_wait<1>(); else cp_wait<0>();
        __syncthreads();
        unsigned abase = smb + kc * DPLANE;
        unsigned bbase = smb + VBOFF + b * (2 * BPLANE);
        #pragma unroll
        for (int ko = 0; ko < 2; ko++) {
            unsigned Af[4][4], Bf[2][4][4];
            #pragma unroll
            for (int mt = 0; mt < 4; mt++)
                ldsm4(Af[mt], abase + aBase + mt * 16 * DPIT + ko * 32);
            #pragma unroll
            for (int np = 0; np < 4; np++) {
                ldsm4(Bf[0][np], bbase + bBase + np * 16 * DPIT + ko * 32);
                ldsm4(Bf[1][np], bbase + BPLANE + bBase + np * 16 * DPIT + ko * 32);
            }
            #pragma unroll
            for (int nt = 0; nt < 8; nt++)
                #pragma unroll
                for (int mt = 0; mt < 4; mt++)
                    hmma(acc[mt][nt], Af[mt], &Bf[1][nt >> 1][(nt & 1) * 2]);
            #pragma unroll
            for (int nt = 0; nt < 8; nt++)
                #pragma unroll
                for (int mt = 0; mt < 4; mt++)
                    hmma(acc[mt][nt], Af[mt], &Bf[0][nt >> 1][(nt & 1) * 2]);
        }
        if (kc == 3) {
            int c0 = (u >> 2) * 256;
            #pragma unroll
            for (int mt = 0; mt < 4; mt++) {
                #pragma unroll
                for (int nt = 0; nt < 8; nt++) {
                    int cn = c0 + wn * 64 + nt * 8 + 2 * tig;
                    float2 nn = *(const float2*)&cbn[cn];
                    float* a = acc[mt][nt];
                    ins3(b_[mt * 2], i_[mt * 2], nn.x - 2.f * a[0], cn);
                    ins3(b_[mt * 2], i_[mt * 2], nn.y - 2.f * a[1], cn + 1);
                    ins3(b_[mt * 2 + 1], i_[mt * 2 + 1], nn.x - 2.f * a[2], cn);
                    ins3(b_[mt * 2 + 1], i_[mt * 2 + 1], nn.y - 2.f * a[3], cn + 1);
                    a[0] = a[1] = a[2] = a[3] = 0.f;
                }
            }
        }
        __syncthreads();
        if (u + 2 < 32) loadB(u + 2, b);
    }

    #pragma unroll
    for (int mt = 0; mt < 4; mt++) {
        int r0 = wm * 64 + mt * 16 + g;
        int c3 = (wn * 4 + tig) * 3;
        #pragma unroll
        for (int k = 0; k < 3; k++) {
            sv[r0][c3 + k] = b_[mt * 2][k];         si[r0][c3 + k] = i_[mt * 2][k];
            sv[r0 + 8][c3 + k] = b_[mt * 2 + 1][k]; si[r0 + 8][c3 + k] = i_[mt * 2 + 1][k];
        }
    }
    __syncthreads();

    // warp-per-row screening + cooperative exact recheck
    float maxC = sqrtf(__int_as_float(g_maxnI));
    for (int row = wid; row < 128; row += 8) {
        float m = sv[row][lane];
        if (lane < 16) m = fminf(m, sv[row][32 + lane]);
        #pragma unroll
        for (int o = 16; o > 0; o >>= 1)
            m = fminf(m, __shfl_xor_sync(0xFFFFFFFFu, m, o));
        float E = 2.f * xln[bm + row] * maxC * 1.05f + 1e-3f;
        float thresh = m + 2.f * E;
        // flag if any thread-partition's 3rd-best is in window (coverage uncertain)
        unsigned fb = __ballot_sync(0xFFFFFFFFu,
            (lane < 16) && (sv[row][lane * 3 + 2] <= thresh));
        if (fb) {
            if (lane == 0) { int p = atomicAdd(&nflag, 1); flist[p] = row; }
            continue;
        }
        if (lane == 0) ncand[wid] = 0;
        __syncwarp();
        for (int k = lane; k < 48; k += 32) {
            if (sv[row][k] <= thresh) {
                int p = atomicAdd(&ncand[wid], 1);
                if (p < 16) cand[wid][p] = si[row][k];
            }
        }
        __syncwarp();
        int nc = ncand[wid];
        if (nc > 16) {
            if (lane == 0) { int p = atomicAdd(&nflag, 1); flist[p] = row; }
            continue;
        }
        const float4* xr = (const float4*)(xf + (bm + row) * 128);
        float4 a4 = xr[lane];
        float bd = 3.4e38f; int bi = 0x7fffffff;
        for (int j = 0; j < nc; j++) {
            int c = cand[wid][j];
            float4 c4 = ((const float4*)(cbf + (size_t)c * 128))[lane];
            float s = a4.x * c4.x + a4.y * c4.y + a4.z * c4.z + a4.w * c4.w;
            #pragma unroll
            for (int o = 16; o > 0; o >>= 1) s += __shfl_xor_sync(0xFFFFFFFFu, s, o);
            float de = cbn[c] - 2.f * s;
            if (de < bd || (de == bd && c < bi)) { bd = de; bi = c; }
        }
        if (lane == 0) srow[row] = bi;
    }
    __syncthreads();

    // fallback: cooperative exact full scan for flagged rows (rare)
    for (int j = 0; j < nflag; j++) {
        int row = flist[j];
        float bd = 3.4e38f; int bi = 0x7fffffff;
        const float4* xr = (const float4*)(xf + (bm + row) * 128);
        for (int c = tid * 8; c < tid * 8 + 8; c++) {
            const float4* cr = (const float4*)(cbf + (size_t)c * 128);
            float s = 0.f;
            #pragma unroll 8
            for (int i = 0; i < 32; i++) {
                float4 a4 = xr[i], c4 = cr[i];
                s += a4.x * c4.x + a4.y * c4.y + a4.z * c4.z + a4.w * c4.w;
            }
            float de = cbn[c] - 2.f * s;
            if (de < bd || (de == bd && c < bi)) { bd = de; bi = c; }
        }
        rv[tid] = bd; ri[tid] = bi;
        __syncthreads();
        if (tid == 0) {
            float v = rv[0]; int x = ri[0];
            for (int t = 1; t < 256; t++)
                if (rv[t] < v || (rv[t] == v && ri[t] < x)) { v = rv[t]; x = ri[t]; }
            srow[row] = x;
        }
        __syncthreads();
    }

    // outputs
    for (int it = tid; it < 128 * 512; it += 256) {
        int rr = it >> 9, c4 = it & 511;
        float4 z = make_float4(0.f, 0.f, 0.f, 0.f);
        int bi = srow[rr];
        if ((bi >> 2) == c4) ((float*)&z)[bi & 3] = 1.0f;
        ((float4*)disc)[(bm + rr) * 512 + c4] = z;
    }
    for (int it = tid; it < 128 * 32; it += 256) {
        int rr = it >> 5, c = it & 31;
        ((float4*)quant)[(bm + rr) * 32 + c] = ((const float4*)cbf)[srow[rr] * 32 + c];
    }
    for (int it = tid; it < 128 * 16; it += 256) {
        int rr = it >> 4, c = it & 15;
        ((uint4*)qh)[(bm + rr) * 16 + c] = ((const uint4*)cbh)[srow[rr] * 16 + c];
    }
}

// ---------------------------------------------------------------------------
// FFMA skinny layers (32x128 tile), exact fp32, optional fp16 hi/lo epilogue
// ---------------------------------------------------------------------------
__global__ __launch_bounds__(256) void dense_lrelu_32(
    const float* __restrict__ A, const float* __restrict__ W,
    const float* __restrict__ bias, float* __restrict__ C,
    __half* __restrict__ Chi, __half* __restrict__ Clo,
    int M, int N, int K)
{
    __shared__ float As[2][8][32];
    __shared__ float Bs[2][8][128];
    int tid = threadIdx.x, tx = tid & 15, ty = tid >> 4;
    int bm = blockIdx.y * 32, bn = blockIdx.x * 128;
    int arow = tid >> 3, acol = tid & 7;
    int wrow = tid >> 5, wcol = (tid & 31) * 4;

    unsigned long long acc[2][4];
    #pragma unroll
    for (int i = 0; i < 2; i++)
        #pragma unroll
        for (int j = 0; j < 4; j++) acc[i][j] = 0ULL;

    const float* Ap = A + (size_t)(bm + arow) * K + acol;
    const float* Wp = W + (size_t)wrow * N + bn + wcol;
    size_t wstep = (size_t)8 * N;
    int T = K >> 3;
    float areg = *Ap;  Ap += 8;
    cp16(sm_u32(&Bs[0][wrow][wcol]), Wp); Wp += wstep;
    cp_commit();

    for (int i = 0; i < T; i++) {
        int cur = i & 1;
        As[cur][acol][arow] = areg;
        if (i + 1 < T) {
            areg = *Ap;  Ap += 8;
            cp16(sm_u32(&Bs[cur ^ 1][wrow][wcol]), Wp); Wp += wstep;
            cp_commit();
            cp_wait<1>();
        } else cp_wait<0>();
        __syncthreads();
        #pragma unroll
        for (int kk = 0; kk < 8; kk++) {
            float2 a2 = *(const float2*)&As[cur][kk][ty * 2];
            float4 b0 = *(const float4*)&Bs[cur][kk][tx * 4];
            float4 b1 = *(const float4*)&Bs[cur][kk][64 + tx * 4];
            unsigned long long bp[4] = { pack2(b0.x, b0.y), pack2(b0.z, b0.w),
                                         pack2(b1.x, b1.y), pack2(b1.z, b1.w) };
            unsigned long long a0 = pack2(a2.x, a2.x), a1 = pack2(a2.y, a2.y);
            fma2(acc[0][0], a0, bp[0]); fma2(acc[0][1], a0, bp[1]);
            fma2(acc[0][2], a0, bp[2]); fma2(acc[0][3], a0, bp[3]);
            fma2(acc[1][0], a1, bp[0]); fma2(acc[1][1], a1, bp[1]);
            fma2(acc[1][2], a1, bp[2]); fma2(acc[1][3], a1, bp[3]);
        }
        __syncthreads();
    }

    float bb0[4], bb1[4];
    #pragma unroll
    for (int j = 0; j < 4; j++) {
        bb0[j] = __ldg(&bias[bn + tx * 4 + j]);
        bb1[j] = __ldg(&bias[bn + 64 + tx * 4 + j]);
    }
    #pragma unroll
    for (int i = 0; i < 2; i++) {
        int r = bm + ty * 2 + i;
        float2 p0 = unpack2(acc[i][0]), p1 = unpack2(acc[i][1]);
        float2 p2 = unpack2(acc[i][2]), p3 = unpack2(acc[i][3]);
        float o[8];
        o[0] = lrelu(p0.x + bb0[0]); o[1] = lrelu(p0.y + bb0[1]);
        o[2] = lrelu(p1.x + bb0[2]); o[3] = lrelu(p1.y + bb0[3]);
        o[4] = lrelu(p2.x + bb1[0]); o[5] = lrelu(p2.y + bb1[1]);
        o[6] = lrelu(p3.x + bb1[2]); o[7] = lrelu(p3.y + bb1[3]);
        *(float4*)&C[(size_t)r * N + bn + tx * 4]      = make_float4(o[0], o[1], o[2], o[3]);
        *(float4*)&C[(size_t)r * N + bn + 64 + tx * 4] = make_float4(o[4], o[5], o[6], o[7]);
        if (Chi) {
            #pragma unroll
            for (int j = 0; j < 8; j++) {
                int cc = bn + ((j < 4) ? 0 : 64) + tx * 4 + (j & 3);
                __half h, l; f16split(o[j], h, l);
                Chi[(size_t)r * N + cc] = h;
                Clo[(size_t)r * N + cc] = l;
            }
        }
    }
}

// ---------------------------------------------------------------------------
extern "C" void kernel_launch(void* const* d_in, const int* in_sizes, int n_in,
                              void* d_out, int out_size) {
    const float* cond = (const float*)d_in[0];
    const float* cb   = (const float*)d_in[1];
    const float* We1  = (const float*)d_in[2];  const float* be1 = (const float*)d_in[3];
    const float* We2  = (const float*)d_in[4];  const float* be2 = (const float*)d_in[5];
    const float* We3  = (const float*)d_in[6];  const float* be3 = (const float*)d_in[7];
    const float* We4  = (const float*)d_in[8];  const float* be4 = (const float*)d_in[9];
    const float* Wd1  = (const float*)d_in[10]; const float* bd1 = (const float*)d_in[11];
    const float* Wd2  = (const float*)d_in[12]; const float* bd2 = (const float*)d_in[13];
    const float* Wd3  = (const float*)d_in[14]; const float* bd3 = (const float*)d_in[15];
    const float* Wd4  = (const float*)d_in[16]; const float* bd4 = (const float*)d_in[17];

    float* out   = (float*)d_out;
    float* recon = out;
    float* enc   = recon + (size_t)BQ * 256;
    float* disc  = enc   + (size_t)BQ * LE;
    float* quant = disc  + (size_t)NROWS * KCB;

    float *x1, *bf, *cbn, *xln;
    __half *x1h, *x1l, *h1, *l1, *h2, *l2;
    __half *w2h, *w2l, *w3h, *w3l, *w4h, *w4l, *d1h, *d1l, *d2h, *d2l, *d3h, *d3l, *cbh, *cbl;
    cudaGetSymbolAddress((void**)&x1,  g_x1);  cudaGetSymbolAddress((void**)&bf,  g_bf);
    cudaGetSymbolAddress((void**)&x1h, g_x1h); cudaGetSymbolAddress((void**)&x1l, g_x1l);
    cudaGetSymbolAddress((void**)&h1,  g_h1);  cudaGetSymbolAddress((void**)&l1,  g_l1);
    cudaGetSymbolAddress((void**)&h2,  g_h2);  cudaGetSymbolAddress((void**)&l2,  g_l2);
    cudaGetSymbolAddress((void**)&w2h, g_w2h); cudaGetSymbolAddress((void**)&w2l, g_w2l);
    cudaGetSymbolAddress((void**)&w3h, g_w3h); cudaGetSymbolAddress((void**)&w3l, g_w3l);
    cudaGetSymbolAddress((void**)&w4h, g_w4h); cudaGetSymbolAddress((void**)&w4l, g_w4l);
    cudaGetSymbolAddress((void**)&d1h, g_d1h); cudaGetSymbolAddress((void**)&d1l, g_d1l);
    cudaGetSymbolAddress((void**)&d2h, g_d2h); cudaGetSymbolAddress((void**)&d2l, g_d2l);
    cudaGetSymbolAddress((void**)&d3h, g_d3h); cudaGetSymbolAddress((void**)&d3l, g_d3l);
    cudaGetSymbolAddress((void**)&cbh, g_cbh); cudaGetSymbolAddress((void**)&cbl, g_cbl);
    cudaGetSymbolAddress((void**)&cbn, g_cbn); cudaGetSymbolAddress((void**)&xln, g_xln);

    cudaFuncSetAttribute(hmma_dense,   cudaFuncAttributeMaxDynamicSharedMemorySize, DSMEM);
    cudaFuncSetAttribute(hmma_partial, cudaFuncAttributeMaxDynamicSharedMemorySize, DSMEM);
    cudaFuncSetAttribute(hmma_vq,      cudaFuncAttributeMaxDynamicSharedMemorySize, VSMEM);

    wtsplit_kernel<<<dim3(64, 2),  256>>>(We2, w2h, w2l, EE, LE);                       // 0
    dense_lrelu_32<<<dim3(1, 128), 256>>>(cond, We1, be1, x1, x1h, x1l, BQ, EE, 256);   // 1
    wtsplit_kernel<<<dim3(64, 32), 256>>>(We3, w3h, w3l, LE, LE);                       // 2
    hmma_dense<<<dim3(16, 32), 128, DSMEM>>>(x1h, x1l, w2h, w2l, be2, nullptr, h1, l1, BQ, LE, EE);  // 3 (profiled)
    hmma_dense<<<dim3(16, 32), 128, DSMEM>>>(h1, l1, w3h, w3l, be3, nullptr, h2, l2, BQ, LE, LE);    // 4
    wtsplit_kernel<<<dim3(64, 32), 256>>>(We4, w4h, w4l, LE, LE);                       // 5
    hmma_dense<<<dim3(16, 32), 128, DSMEM>>>(h2, l2, w4h, w4l, be4, enc, h1, l1, BQ, LE, LE);        // 6
    xln_kernel<<<NROWS / 8, 256>>>(l1, xln);                                            // 7
    cbsplit_kernel<<<KCB, 128>>>(cb, cbh, cbl, cbn);                                    // 8
    wtsplit_kernel<<<dim3(64, 32), 256>>>(Wd1, d1h, d1l, LE, LE);                       // 9
    wtsplit_kernel<<<dim3(64, 32), 256>>>(Wd2, d2h, d2l, LE, LE);                       // 10
    wtsplit_kernel<<<dim3(4, 32),  256>>>(Wd3, d3h, d3l, LE, EE);                       // 11
    // VQ: 2-pass screened, exact argmin (warp-cooperative epilogue)
    hmma_vq<<<NROWS / 128, 256, VSMEM>>>(h1, cbh, cbl, cbn, cb, enc, xln, quant, disc, h2); // 12
    // decoder: Wd1 1-pass, Wd2 1-pass, Wd3 split-K 1-pass, Wd4 exact FFMA
    hmma_dense<<<dim3(16, 32), 128, DSMEM>>>(h2, nullptr, d1h, nullptr, bd1, nullptr, h1, nullptr, BQ, LE, LE); // 13
    hmma_dense<<<dim3(16, 32), 128, DSMEM>>>(h1, nullptr, d2h, nullptr, bd2, nullptr, h2, nullptr, BQ, LE, LE); // 14
    hmma_partial<<<dim3(1, 32, 8), 128, DSMEM>>>(h2, d3h, nullptr, bf, BQ, EE, LE, 256); // 15
    reduceK_kernel<<<(BQ * EE / 4 + 255) / 256, 256>>>(bf, bd3, x1, BQ * EE, EE, 8);    // 16
    dense_lrelu_32<<<dim3(2, 128), 256>>>(x1, Wd4, bd4, recon, nullptr, nullptr, BQ, 256, EE); // 17
}

// round 15
// speedup vs baseline: 1.1164x; 1.0884x over previous
#include <cuda_runtime.h>
#include <cuda_fp16.h>

#define BQ 4096
#define LE 2048
#define EE 128
#define KCB 2048
#define NROWS 65536

// ---- scratch ---------------------------------------------------------------
__device__ float  g_x1 [BQ * EE];
__device__ __half g_x1h[BQ * EE];
__device__ __half g_x1l[BQ * EE];
__device__ float  g_bf [BQ * LE];          // split-K partial scratch
__device__ __half g_h1 [BQ * LE];
__device__ __half g_l1 [BQ * LE];
__device__ __half g_h2 [BQ * LE];
__device__ __half g_l2 [BQ * LE];
__device__ __half g_w2h[LE * EE],  g_w2l[LE * EE];
__device__ __half g_w3h[LE * LE],  g_w3l[LE * LE];
__device__ __half g_w4h[LE * LE],  g_w4l[LE * LE];
__device__ __half g_d1h[LE * LE],  g_d1l[LE * LE];
__device__ __half g_d2h[LE * LE],  g_d2l[LE * LE];
__device__ __half g_d3h[EE * LE],  g_d3l[EE * LE];
__device__ __half g_cbh[KCB * EE], g_cbl[KCB * EE];
__device__ float  g_cbn[KCB];

__device__ __forceinline__ float lrelu(float v) { return fmaxf(v, 0.2f * v); }

__device__ __forceinline__ void f16split(float x, __half& h, __half& l) {
    h = __float2half_rn(x);
    l = __float2half_rn(x - __half2float(h));
}
__device__ __forceinline__ unsigned sm_u32(const void* p) {
    return (unsigned)__cvta_generic_to_shared(p);
}
__device__ __forceinline__ void cp16(unsigned s, const void* g) {
    asm volatile("cp.async.cg.shared.global [%0], [%1], 16;" :: "r"(s), "l"(g));
}
__device__ __forceinline__ void cp_commit() { asm volatile("cp.async.commit_group;"); }
template<int N> __device__ __forceinline__ void cp_wait() {
    asm volatile("cp.async.wait_group %0;" :: "n"(N));
}
__device__ __forceinline__ void hmma(float* c, const unsigned* a, const unsigned* b) {
    asm volatile(
        "mma.sync.aligned.m16n8k16.row.col.f32.f16.f16.f32 "
        "{%0,%1,%2,%3}, {%4,%5,%6,%7}, {%8,%9}, {%0,%1,%2,%3};"
        : "+f"(c[0]), "+f"(c[1]), "+f"(c[2]), "+f"(c[3])
        : "r"(a[0]), "r"(a[1]), "r"(a[2]), "r"(a[3]), "r"(b[0]), "r"(b[1]));
}
__device__ __forceinline__ void ldsm4(unsigned* r, unsigned addr) {
    asm volatile("ldmatrix.sync.aligned.m8n8.x4.shared.b16 {%0,%1,%2,%3}, [%4];"
        : "=r"(r[0]), "=r"(r[1]), "=r"(r[2]), "=r"(r[3]) : "r"(addr));
}
// ---- packed fp32x2 (skinny FFMA path) --------------------------------------
__device__ __forceinline__ unsigned long long pack2(float lo, float hi) {
    unsigned long long r;
    asm("mov.b64 %0, {%1, %2};" : "=l"(r) : "f"(lo), "f"(hi));
    return r;
}
__device__ __forceinline__ void fma2(unsigned long long& a,
                                     unsigned long long x, unsigned long long y) {
    asm("fma.rn.f32x2 %0, %1, %2, %0;" : "+l"(a) : "l"(x), "l"(y));
}
__device__ __forceinline__ float2 unpack2(unsigned long long v) {
    float lo, hi;
    asm("mov.b64 {%0, %1}, %2;" : "=f"(lo), "=f"(hi) : "l"(v));
    return make_float2(lo, hi);
}

// ---------------------------------------------------------------------------
// prep: W[K,N] -> [N,K] fp16 hi/lo, 64k x 32n tiles, half2 stores (128B rows)
// ---------------------------------------------------------------------------
__global__ void wtsplit_kernel(const float* __restrict__ W, __half* __restrict__ Th,
                               __half* __restrict__ Tl, int K, int N) {
    __shared__ float t[64][33];
    int n0 = blockIdx.x * 32, k0 = blockIdx.y * 64;
    int tx = threadIdx.x & 31, tr = threadIdx.x >> 5;
    for (int r = tr; r < 64; r += 8) t[r][tx] = W[(size_t)(k0 + r) * N + n0 + tx];
    __syncthreads();
    for (int r2 = tr; r2 < 32; r2 += 8) {
        __half h0, l0, h1, l1;
        f16split(t[2 * tx][r2], h0, l0);
        f16split(t[2 * tx + 1][r2], h1, l1);
        *(__half2*)&Th[(size_t)(n0 + r2) * K + k0 + 2 * tx] = __halves2half2(h0, h1);
        *(__half2*)&Tl[(size_t)(n0 + r2) * K + k0 + 2 * tx] = __halves2half2(l0, l1);
    }
}
__global__ void cbsplit_kernel(const float* __restrict__ cb, __half* __restrict__ hi,
                               __half* __restrict__ lo, float* __restrict__ nrm) {
    int n = blockIdx.x, e = threadIdx.x;
    float v = cb[n * EE + e];
    __half h, l; f16split(v, h, l);
    hi[n * EE + e] = h;
    lo[n * EE + e] = l;
    float q = v * v;
    #pragma unroll
    for (int o = 16; o > 0; o >>= 1) q += __shfl_xor_sync(0xFFFFFFFFu, q, o);
    __shared__ float ws[4];
    if ((e & 31) == 0) ws[e >> 5] = q;
    __syncthreads();
    if (e == 0) nrm[n] = ws[0] + ws[1] + ws[2] + ws[3];
}

// ---------------------------------------------------------------------------
// FP16 dense: 128 threads, 4 warps (2x2 of 64x64), BK=32.
// Pass count by null args: Al null -> drop Al*Bh; Bl null -> drop Ah*Bl.
// ---------------------------------------------------------------------------
#define DPIT   80
#define DPLANE 10240
#define DBUF   40960
#define DSMEM  81920

__global__ __launch_bounds__(128, 2) void hmma_dense(
    const __half* __restrict__ Ah, const __half* __restrict__ Al,
    const __half* __restrict__ Bh, const __half* __restrict__ Bl,
    const float* __restrict__ bias,
    float* __restrict__ Cf, __half* __restrict__ Ch, __half* __restrict__ Cl,
    int M, int N, int K)
{
    extern __shared__ char dsm[];
    unsigned smb = sm_u32(dsm);
    int tid = threadIdx.x, lane = tid & 31, wid = tid >> 5;
    int wm = wid >> 1, wn = wid & 1, g = lane >> 2, tig = lane & 3;
    int bm = blockIdx.y * 128, bn = blockIdx.x * 128;
    bool aLo = (Al != nullptr), bLo = (Bl != nullptr);

    const __half* P[4] = { Ah + (size_t)bm * K, aLo ? Al + (size_t)bm * K : nullptr,
                           Bh + (size_t)bn * K, bLo ? Bl + (size_t)bn * K : nullptr };

    float acc[4][8][4];
    #pragma unroll
    for (int i = 0; i < 4; i++)
        #pragma unroll
        for (int j = 0; j < 8; j++)
            #pragma unroll
            for (int q = 0; q < 4; q++) acc[i][j][q] = 0.f;

    unsigned aBase = (wm * 64 + (lane & 15)) * DPIT + ((lane >> 4) & 1) * 16;
    unsigned bBase = 2 * DPLANE + (wn * 64 + ((lane >> 4) & 1) * 8 + (lane & 7)) * DPIT
                     + ((lane >> 3) & 1) * 16;

    auto load_stage = [&](int u, int b) {
        #pragma unroll
        for (int i = 0; i < 16; i++) {
            int cid = i * 128 + tid;
            int p = cid >> 9, rem = cid & 511, row = rem >> 2, c = rem & 3;
            if (P[p])
                cp16(smb + b * DBUF + p * DPLANE + row * DPIT + c * 16,
                     P[p] + (size_t)row * K + u * 32 + c * 8);
        }
        cp_commit();
    };

    int S = K >> 5;
    load_stage(0, 0);
    load_stage(1, 1);

    for (int s = 0; s < S; s++) {
        int b = s & 1;
        if (s + 1 < S) cp_wait<1>(); else cp_wait<0>();
        __syncthreads();
        unsigned base = smb + b * DBUF;
        #pragma unroll
        for (int ko = 0; ko < 2; ko++) {
            unsigned Af[2][4][4], Bf[2][4][4];
            #pragma unroll
            for (int mt = 0; mt < 4; mt++) {
                ldsm4(Af[0][mt], base + aBase + mt * 16 * DPIT + ko * 32);
                if (aLo)
                    ldsm4(Af[1][mt], base + DPLANE + aBase + mt * 16 * DPIT + ko * 32);
            }
            #pragma unroll
            for (int np = 0; np < 4; np++) {
                ldsm4(Bf[0][np], base + bBase + np * 16 * DPIT + ko * 32);
                if (bLo)
                    ldsm4(Bf[1][np], base + DPLANE + bBase + np * 16 * DPIT + ko * 32);
            }
            if (aLo) {
                #pragma unroll
                for (int nt = 0; nt < 8; nt++)
                    #pragma unroll
                    for (int mt = 0; mt < 4; mt++)
                        hmma(acc[mt][nt], Af[1][mt], &Bf[0][nt >> 1][(nt & 1) * 2]);
            }
            if (bLo) {
                #pragma unroll
                for (int nt = 0; nt < 8; nt++)
                    #pragma unroll
                    for (int mt = 0; mt < 4; mt++)
                        hmma(acc[mt][nt], Af[0][mt], &Bf[1][nt >> 1][(nt & 1) * 2]);
            }
            #pragma unroll
            for (int nt = 0; nt < 8; nt++)
                #pragma unroll
                for (int mt = 0; mt < 4; mt++)
                    hmma(acc[mt][nt], Af[0][mt], &Bf[0][nt >> 1][(nt & 1) * 2]);
        }
        __syncthreads();
        if (s + 2 < S) load_stage(s + 2, b);
    }

    #pragma unroll
    for (int mt = 0; mt < 4; mt++) {
        int r0 = bm + wm * 64 + mt * 16 + g;
        int r1 = r0 + 8;
        #pragma unroll
        for (int nt = 0; nt < 8; nt++) {
            int cn = bn + wn * 64 + nt * 8 + 2 * tig;
            float2 bv = *(const float2*)&bias[cn];
            float o0 = lrelu(acc[mt][nt][0] + bv.x);
            float o1 = lrelu(acc[mt][nt][1] + bv.y);
            float o2 = lrelu(acc[mt][nt][2] + bv.x);
            float o3 = lrelu(acc[mt][nt][3] + bv.y);
            if (Cf) {
                *(float2*)&Cf[(size_t)r0 * N + cn] = make_float2(o0, o1);
                *(float2*)&Cf[(size_t)r1 * N + cn] = make_float2(o2, o3);
            }
            if (Ch) {
                __half h0, l0, h1, l1, h2v, l2v, h3, l3;
                f16split(o0, h0, l0); f16split(o1, h1, l1);
                f16split(o2, h2v, l2v); f16split(o3, h3, l3);
                *(__half2*)&Ch[(size_t)r0 * N + cn] = __halves2half2(h0, h1);
                *(__half2*)&Ch[(size_t)r1 * N + cn] = __halves2half2(h2v, h3);
                if (Cl) {
                    *(__half2*)&Cl[(size_t)r0 * N + cn] = __halves2half2(l0, l1);
                    *(__half2*)&Cl[(size_t)r1 * N + cn] = __halves2half2(l2v, l3);
                }
            }
        }
    }
}

// ---------------------------------------------------------------------------
// Split-K HMMA (Wd3): Bl null -> 1-pass. Raw fp32 partials.
// ---------------------------------------------------------------------------
__global__ __launch_bounds__(128, 2) void hmma_partial(
    const __half* __restrict__ Ah,
    const __half* __restrict__ Bh, const __half* __restrict__ Bl,
    float* __restrict__ Cp, int M, int N, int K, int KC)
{
    extern __shared__ char dsm[];
    unsigned smb = sm_u32(dsm);
    int tid = threadIdx.x, lane = tid & 31, wid = tid >> 5;
    int wm = wid >> 1, wn = wid & 1, g = lane >> 2, tig = lane & 3;
    int bm = blockIdx.y * 128, bn = blockIdx.x * 128;
    int kOff = blockIdx.z * KC;
    bool bLo = (Bl != nullptr);

    const __half* P[4] = { Ah + (size_t)bm * K + kOff, nullptr,
                           Bh + (size_t)bn * K + kOff, bLo ? Bl + (size_t)bn * K + kOff : nullptr };

    float acc[4][8][4];
    #pragma unroll
    for (int i = 0; i < 4; i++)
        #pragma unroll
        for (int j = 0; j < 8; j++)
            #pragma unroll
            for (int q = 0; q < 4; q++) acc[i][j][q] = 0.f;

    unsigned aBase = (wm * 64 + (lane & 15)) * DPIT + ((lane >> 4) & 1) * 16;
    unsigned bBase = 2 * DPLANE + (wn * 64 + ((lane >> 4) & 1) * 8 + (lane & 7)) * DPIT
                     + ((lane >> 3) & 1) * 16;

    auto load_stage = [&](int u, int b) {
        #pragma unroll
        for (int i = 0; i < 16; i++) {
            int cid = i * 128 + tid;
            int p = cid >> 9, rem = cid & 511, row = rem >> 2, c = rem & 3;
            if (P[p])
                cp16(smb + b * DBUF + p * DPLANE + row * DPIT + c * 16,
                     P[p] + (size_t)row * K + u * 32 + c * 8);
        }
        cp_commit();
    };

    int S = KC >> 5;
    load_stage(0, 0);
    load_stage(1, 1);

    for (int s = 0; s < S; s++) {
        int b = s & 1;
        if (s + 1 < S) cp_wait<1>(); else cp_wait<0>();
        __syncthreads();
        unsigned base = smb + b * DBUF;
        #pragma unroll
        for (int ko = 0; ko < 2; ko++) {
            unsigned Af[4][4], Bf[2][4][4];
            #pragma unroll
            for (int mt = 0; mt < 4; mt++)
                ldsm4(Af[mt], base + aBase + mt * 16 * DPIT + ko * 32);
            #pragma unroll
            for (int np = 0; np < 4; np++) {
                ldsm4(Bf[0][np], base + bBase + np * 16 * DPIT + ko * 32);
                if (bLo)
                    ldsm4(Bf[1][np], base + DPLANE + bBase + np * 16 * DPIT + ko * 32);
            }
            if (bLo) {
                #pragma unroll
                for (int nt = 0; nt < 8; nt++)
                    #pragma unroll
                    for (int mt = 0; mt < 4; mt++)
                        hmma(acc[mt][nt], Af[mt], &Bf[1][nt >> 1][(nt & 1) * 2]);
            }
            #pragma unroll
            for (int nt = 0; nt < 8; nt++)
                #pragma unroll
                for (int mt = 0; mt < 4; mt++)
                    hmma(acc[mt][nt], Af[mt], &Bf[0][nt >> 1][(nt & 1) * 2]);
        }
        __syncthreads();
        if (s + 2 < S) load_stage(s + 2, b);
    }

    size_t zbase = (size_t)blockIdx.z * M * N;
    #pragma unroll
    for (int mt = 0; mt < 4; mt++) {
        int r0 = bm + wm * 64 + mt * 16 + g;
        int r1 = r0 + 8;
        #pragma unroll
        for (int nt = 0; nt < 8; nt++) {
            int cn = bn + wn * 64 + nt * 8 + 2 * tig;
            *(float2*)&Cp[zbase + (size_t)r0 * N + cn] = make_float2(acc[mt][nt][0], acc[mt][nt][1]);
            *(float2*)&Cp[zbase + (size_t)r1 * N + cn] = make_float2(acc[mt][nt][2], acc[mt][nt][3]);
        }
    }
}

__global__ void reduceK_kernel(const float* __restrict__ Cp, const float* __restrict__ bias,
                               float* __restrict__ X, int MN, int N, int Z) {
    int i4 = blockIdx.x * 256 + threadIdx.x;
    int n4 = MN >> 2;
    if (i4 >= n4) return;
    const float4* C4 = (const float4*)Cp;
    float4 s = C4[i4];
    for (int z = 1; z < Z; z++) {
        float4 v = C4[(size_t)z * n4 + i4];
        s.x += v.x; s.y += v.y; s.z += v.z; s.w += v.w;
    }
    int col = (i4 * 4) & (N - 1);
    float4 bv = *(const float4*)&bias[col];
    float4 o;
    o.x = lrelu(s.x + bv.x); o.y = lrelu(s.y + bv.y);
    o.z = lrelu(s.z + bv.z); o.w = lrelu(s.w + bv.w);
    ((float4*)X)[i4] = o;
}

// ---------------------------------------------------------------------------
// 3xFP16 VQ (R12's proven 1406us version): 256 threads, 8 warps (2x4 of 64x64),
// 256-codeword slabs, simple per-thread argmin, fused one-hot + gather.
// ---------------------------------------------------------------------------
#define BPLANE 20480
#define VBOFF  81920
#define VSMEM  (VBOFF + 2 * 2 * BPLANE)   // 163840

__global__ __launch_bounds__(256, 1) void hmma_vq(
    const __half* __restrict__ Ah, const __half* __restrict__ Al,
    const __half* __restrict__ cbh, const __half* __restrict__ cbl,
    const float* __restrict__ cbn, const float* __restrict__ cbf,
    float* __restrict__ quant, float* __restrict__ disc,
    __half* __restrict__ qh)
{
    extern __shared__ char dsm[];
    unsigned smb = sm_u32(dsm);
    __shared__ float sv[128][16];
    __shared__ int   si[128][16];
    __shared__ int   srow[128];
    int tid = threadIdx.x, lane = tid & 31, wid = tid >> 5;
    int wm = wid >> 2, wn = wid & 3, g = lane >> 2, tig = lane & 3;
    long bm = (long)blockIdx.x * 128;

    float acc[4][8][4];
    #pragma unroll
    for (int i = 0; i < 4; i++)
        #pragma unroll
        for (int j = 0; j < 8; j++)
            #pragma unroll
            for (int q = 0; q < 4; q++) acc[i][j][q] = 0.f;

    float bestv[8];
    int   besti[8];
    #pragma unroll
    for (int i = 0; i < 8; i++) { bestv[i] = 3.4e38f; besti[i] = 0; }

    unsigned aBase = (wm * 64 + (lane & 15)) * DPIT + ((lane >> 4) & 1) * 16;
    unsigned bBase = (wn * 64 + ((lane >> 4) & 1) * 8 + (lane & 7)) * DPIT
                     + ((lane >> 3) & 1) * 16;

    #pragma unroll
    for (int i = 0; i < 16; i++) {
        int cid = i * 256 + tid;
        int p = cid >> 9, rem = cid & 511, row = rem >> 2, c = rem & 3;
        const __half* base = (p >= 4) ? Al : Ah;
        cp16(smb + p * DPLANE + row * DPIT + c * 16,
             base + (bm + row) * 128 + (p & 3) * 32 + c * 8);
    }
    cp_commit();

    auto loadB = [&](int u, int b) {
        int slab = u >> 2, kc = u & 3;
        #pragma unroll
        for (int i = 0; i < 8; i++) {
            int cid = i * 256 + tid;
            int pl = cid >> 10, rem = cid & 1023, row = rem >> 2, c = rem & 3;
            const __half* base = pl ? cbl : cbh;
            cp16(smb + VBOFF + b * (2 * BPLANE) + pl * BPLANE + row * DPIT + c * 16,
                 base + (size_t)(slab * 256 + row) * 128 + kc * 32 + c * 8);
        }
        cp_commit();
    };
    loadB(0, 0);
    loadB(1, 1);

    for (int u = 0; u < 32; u++) {
        int b = u & 1, kc = u & 3;
        if (u + 1 < 32) cp_wait<1>(); else cp_wait<0>();
        __syncthreads();
        unsigned abase = smb + kc * DPLANE;
        unsigned bbase = smb + VBOFF + b * (2 * BPLANE);
        #pragma unroll
        for (int ko = 0; ko < 2; ko++) {
            unsigned Af[2][4][4], Bf[2][4][4];
            #pragma unroll
            for (int mt = 0; mt < 4; mt++) {
                ldsm4(Af[0][mt], abase + aBase + mt * 16 * DPIT + ko * 32);
                ldsm4(Af[1][mt], abase + 4 * DPLANE + aBase + mt * 16 * DPIT + ko * 32);
            }
            #pragma unroll
            for (int np = 0; np < 4; np++) {
                ldsm4(Bf[0][np], bbase + bBase + np * 16 * DPIT + ko * 32);
                ldsm4(Bf[1][np], bbase + BPLANE + bBase + np * 16 * DPIT + ko * 32);
            }
            #pragma unroll
            for (int nt = 0; nt < 8; nt++)
                #pragma unroll
                for (int mt = 0; mt < 4; mt++)
                    hmma(acc[mt][nt], Af[1][mt], &Bf[0][nt >> 1][(nt & 1) * 2]);
            #pragma unroll
            for (int nt = 0; nt < 8; nt++)
                #pragma unroll
                for (int mt = 0; mt < 4; mt++)
                    hmma(acc[mt][nt], Af[0][mt], &Bf[1][nt >> 1][(nt & 1) * 2]);
            #pragma unroll
            for (int nt = 0; nt < 8; nt++)
                #pragma unroll
                for (int mt = 0; mt < 4; mt++)
                    hmma(acc[mt][nt], Af[0][mt], &Bf[0][nt >> 1][(nt & 1) * 2]);
        }
        if (kc == 3) {
            int c0 = (u >> 2) * 256;
            #pragma unroll
            for (int mt = 0; mt < 4; mt++) {
                #pragma unroll
                for (int nt = 0; nt < 8; nt++) {
                    int cn = c0 + wn * 64 + nt * 8 + 2 * tig;
                    float2 nn = *(const float2*)&cbn[cn];
                    float* a = acc[mt][nt];
                    float d0 = nn.x - 2.f * a[0];
                    if (d0 < bestv[mt * 2]) { bestv[mt * 2] = d0; besti[mt * 2] = cn; }
                    float d1 = nn.y - 2.f * a[1];
                    if (d1 < bestv[mt * 2]) { bestv[mt * 2] = d1; besti[mt * 2] = cn + 1; }
                    float d2 = nn.x - 2.f * a[2];
                    if (d2 < bestv[mt * 2 + 1]) { bestv[mt * 2 + 1] = d2; besti[mt * 2 + 1] = cn; }
                    float d3 = nn.y - 2.f * a[3];
                    if (d3 < bestv[mt * 2 + 1]) { bestv[mt * 2 + 1] = d3; besti[mt * 2 + 1] = cn + 1; }
                    a[0] = a[1] = a[2] = a[3] = 0.f;
                }
            }
        }
        __syncthreads();
        if (u + 2 < 32) loadB(u + 2, b);
    }

    #pragma unroll
    for (int mt = 0; mt < 4; mt++) {
        int r0 = wm * 64 + mt * 16 + g;
        int col = wn * 4 + tig;
        sv[r0][col] = bestv[mt * 2];         si[r0][col] = besti[mt * 2];
        sv[r0 + 8][col] = bestv[mt * 2 + 1]; si[r0 + 8][col] = besti[mt * 2 + 1];
    }
    __syncthreads();
    if (tid < 128) {
        float bv = sv[tid][0];
        int   bi = si[tid][0];
        #pragma unroll
        for (int t = 1; t < 16; t++) {
            float v = sv[tid][t];
            int  ix = si[tid][t];
            if (v < bv || (v == bv && ix < bi)) { bv = v; bi = ix; }
        }
        srow[tid] = bi;
    }
    __syncthreads();

    for (int it = tid; it < 128 * 512; it += 256) {
        int rr = it >> 9, c4 = it & 511;
        float4 z = make_float4(0.f, 0.f, 0.f, 0.f);
        int bi = srow[rr];
        if ((bi >> 2) == c4) ((float*)&z)[bi & 3] = 1.0f;
        ((float4*)disc)[(bm + rr) * 512 + c4] = z;
    }
    for (int it = tid; it < 128 * 32; it += 256) {
        int rr = it >> 5, c = it & 31;
        ((float4*)quant)[(bm + rr) * 32 + c] = ((const float4*)cbf)[srow[rr] * 32 + c];
    }
    for (int it = tid; it < 128 * 16; it += 256) {
        int rr = it >> 4, c = it & 15;
        ((uint4*)qh)[(bm + rr) * 16 + c] = ((const uint4*)cbh)[srow[rr] * 16 + c];
    }
}

// ---------------------------------------------------------------------------
// FFMA skinny layers (32x128 tile), exact fp32, optional fp16 hi/lo epilogue
// ---------------------------------------------------------------------------
__global__ __launch_bounds__(256) void dense_lrelu_32(
    const float* __restrict__ A, const float* __restrict__ W,
    const float* __restrict__ bias, float* __restrict__ C,
    __half* __restrict__ Chi, __half* __restrict__ Clo,
    int M, int N, int K)
{
    __shared__ float As[2][8][32];
    __shared__ float Bs[2][8][128];
    int tid = threadIdx.x, tx = tid & 15, ty = tid >> 4;
    int bm = blockIdx.y * 32, bn = blockIdx.x * 128;
    int arow = tid >> 3, acol = tid & 7;
    int wrow = tid >> 5, wcol = (tid & 31) * 4;

    unsigned long long acc[2][4];
    #pragma unroll
    for (int i = 0; i < 2; i++)
        #pragma unroll
        for (int j = 0; j < 4; j++) acc[i][j] = 0ULL;

    const float* Ap = A + (size_t)(bm + arow) * K + acol;
    const float* Wp = W + (size_t)wrow * N + bn + wcol;
    size_t wstep = (size_t)8 * N;
    int T = K >> 3;
    float areg = *Ap;  Ap += 8;
    cp16(sm_u32(&Bs[0][wrow][wcol]), Wp); Wp += wstep;
    cp_commit();

    for (int i = 0; i < T; i++) {
        int cur = i & 1;
        As[cur][acol][arow] = areg;
        if (i + 1 < T) {
            areg = *Ap;  Ap += 8;
            cp16(sm_u32(&Bs[cur ^ 1][wrow][wcol]), Wp); Wp += wstep;
            cp_commit();
            cp_wait<1>();
        } else cp_wait<0>();
        __syncthreads();
        #pragma unroll
        for (int kk = 0; kk < 8; kk++) {
            float2 a2 = *(const float2*)&As[cur][kk][ty * 2];
            float4 b0 = *(const float4*)&Bs[cur][kk][tx * 4];
            float4 b1 = *(const float4*)&Bs[cur][kk][64 + tx * 4];
            unsigned long long bp[4] = { pack2(b0.x, b0.y), pack2(b0.z, b0.w),
                                         pack2(b1.x, b1.y), pack2(b1.z, b1.w) };
            unsigned long long a0 = pack2(a2.x, a2.x), a1 = pack2(a2.y, a2.y);
            fma2(acc[0][0], a0, bp[0]); fma2(acc[0][1], a0, bp[1]);
            fma2(acc[0][2], a0, bp[2]); fma2(acc[0][3], a0, bp[3]);
            fma2(acc[1][0], a1, bp[0]); fma2(acc[1][1], a1, bp[1]);
            fma2(acc[1][2], a1, bp[2]); fma2(acc[1][3], a1, bp[3]);
        }
        __syncthreads();
    }

    float bb0[4], bb1[4];
    #pragma unroll
    for (int j = 0; j < 4; j++) {
        bb0[j] = __ldg(&bias[bn + tx * 4 + j]);
        bb1[j] = __ldg(&bias[bn + 64 + tx * 4 + j]);
    }
    #pragma unroll
    for (int i = 0; i < 2; i++) {
        int r = bm + ty * 2 + i;
        float2 p0 = unpack2(acc[i][0]), p1 = unpack2(acc[i][1]);
        float2 p2 = unpack2(acc[i][2]), p3 = unpack2(acc[i][3]);
        float o[8];
        o[0] = lrelu(p0.x + bb0[0]); o[1] = lrelu(p0.y + bb0[1]);
        o[2] = lrelu(p1.x + bb0[2]); o[3] = lrelu(p1.y + bb0[3]);
        o[4] = lrelu(p2.x + bb1[0]); o[5] = lrelu(p2.y + bb1[1]);
        o[6] = lrelu(p3.x + bb1[2]); o[7] = lrelu(p3.y + bb1[3]);
        *(float4*)&C[(size_t)r * N + bn + tx * 4]      = make_float4(o[0], o[1], o[2], o[3]);
        *(float4*)&C[(size_t)r * N + bn + 64 + tx * 4] = make_float4(o[4], o[5], o[6], o[7]);
        if (Chi) {
            #pragma unroll
            for (int j = 0; j < 8; j++) {
                int cc = bn + ((j < 4) ? 0 : 64) + tx * 4 + (j & 3);
                __half h, l; f16split(o[j], h, l);
                Chi[(size_t)r * N + cc] = h;
                Clo[(size_t)r * N + cc] = l;
            }
        }
    }
}

// ---------------------------------------------------------------------------
extern "C" void kernel_launch(void* const* d_in, const int* in_sizes, int n_in,
                              void* d_out, int out_size) {
    const float* cond = (const float*)d_in[0];
    const float* cb   = (const float*)d_in[1];
    const float* We1  = (const float*)d_in[2];  const float* be1 = (const float*)d_in[3];
    const float* We2  = (const float*)d_in[4];  const float* be2 = (const float*)d_in[5];
    const float* We3  = (const float*)d_in[6];  const float* be3 = (const float*)d_in[7];
    const float* We4  = (const float*)d_in[8];  const float* be4 = (const float*)d_in[9];
    const float* Wd1  = (const float*)d_in[10]; const float* bd1 = (const float*)d_in[11];
    const float* Wd2  = (const float*)d_in[12]; const float* bd2 = (const float*)d_in[13];
    const float* Wd3  = (const float*)d_in[14]; const float* bd3 = (const float*)d_in[15];
    const float* Wd4  = (const float*)d_in[16]; const float* bd4 = (const float*)d_in[17];

    float* out   = (float*)d_out;
    float* recon = out;
    float* enc   = recon + (size_t)BQ * 256;
    float* disc  = enc   + (size_t)BQ * LE;
    float* quant = disc  + (size_t)NROWS * KCB;

    float *x1, *bf, *cbn;
    __half *x1h, *x1l, *h1, *l1, *h2, *l2;
    __half *w2h, *w2l, *w3h, *w3l, *w4h, *w4l, *d1h, *d1l, *d2h, *d2l, *d3h, *d3l, *cbh, *cbl;
    cudaGetSymbolAddress((void**)&x1,  g_x1);  cudaGetSymbolAddress((void**)&bf,  g_bf);
    cudaGetSymbolAddress((void**)&x1h, g_x1h); cudaGetSymbolAddress((void**)&x1l, g_x1l);
    cudaGetSymbolAddress((void**)&h1,  g_h1);  cudaGetSymbolAddress((void**)&l1,  g_l1);
    cudaGetSymbolAddress((void**)&h2,  g_h2);  cudaGetSymbolAddress((void**)&l2,  g_l2);
    cudaGetSymbolAddress((void**)&w2h, g_w2h); cudaGetSymbolAddress((void**)&w2l, g_w2l);
    cudaGetSymbolAddress((void**)&w3h, g_w3h); cudaGetSymbolAddress((void**)&w3l, g_w3l);
    cudaGetSymbolAddress((void**)&w4h, g_w4h); cudaGetSymbolAddress((void**)&w4l, g_w4l);
    cudaGetSymbolAddress((void**)&d1h, g_d1h); cudaGetSymbolAddress((void**)&d1l, g_d1l);
    cudaGetSymbolAddress((void**)&d2h, g_d2h); cudaGetSymbolAddress((void**)&d2l, g_d2l);
    cudaGetSymbolAddress((void**)&d3h, g_d3h); cudaGetSymbolAddress((void**)&d3l, g_d3l);
    cudaGetSymbolAddress((void**)&cbh, g_cbh); cudaGetSymbolAddress((void**)&cbl, g_cbl);
    cudaGetSymbolAddress((void**)&cbn, g_cbn);

    cudaFuncSetAttribute(hmma_dense,   cudaFuncAttributeMaxDynamicSharedMemorySize, DSMEM);
    cudaFuncSetAttribute(hmma_partial, cudaFuncAttributeMaxDynamicSharedMemorySize, DSMEM);
    cudaFuncSetAttribute(hmma_vq,      cudaFuncAttributeMaxDynamicSharedMemorySize, VSMEM);

    // wtsplit grid: (N/32, K/64)
    wtsplit_kernel<<<dim3(64, 2),  256>>>(We2, w2h, w2l, EE, LE);                       // 0
    dense_lrelu_32<<<dim3(1, 128), 256>>>(cond, We1, be1, x1, x1h, x1l, BQ, EE, 256);   // 1
    wtsplit_kernel<<<dim3(64, 32), 256>>>(We3, w3h, w3l, LE, LE);                       // 2
    hmma_dense<<<dim3(16, 32), 128, DSMEM>>>(x1h, x1l, w2h, w2l, be2, nullptr, h1, l1, BQ, LE, EE);  // 3 (profiled)
    hmma_dense<<<dim3(16, 32), 128, DSMEM>>>(h1, l1, w3h, w3l, be3, nullptr, h2, l2, BQ, LE, LE);    // 4
    wtsplit_kernel<<<dim3(64, 32), 256>>>(We4, w4h, w4l, LE, LE);                       // 5
    hmma_dense<<<dim3(16, 32), 128, DSMEM>>>(h2, l2, w4h, w4l, be4, enc, h1, l1, BQ, LE, LE);        // 6
    cbsplit_kernel<<<KCB, 128>>>(cb, cbh, cbl, cbn);                                    // 7
    wtsplit_kernel<<<dim3(64, 32), 256>>>(Wd1, d1h, d1l, LE, LE);                       // 8
    wtsplit_kernel<<<dim3(64, 32), 256>>>(Wd2, d2h, d2l, LE, LE);                       // 9
    wtsplit_kernel<<<dim3(4, 32),  256>>>(Wd3, d3h, d3l, LE, EE);                       // 10
    // VQ: 3-pass, simple argmin (R12 proven config)
    hmma_vq<<<NROWS / 128, 256, VSMEM>>>(h1, l1, cbh, cbl, cbn, cb, quant, disc, h2);   // 11
    // decoder: Wd1 1-pass, Wd2 1-pass, Wd3 split-K 1-pass, Wd4 exact FFMA
    hmma_dense<<<dim3(16, 32), 128, DSMEM>>>(h2, nullptr, d1h, nullptr, bd1, nullptr, h1, nullptr, BQ, LE, LE); // 12
    hmma_dense<<<dim3(16, 32), 128, DSMEM>>>(h1, nullptr, d2h, nullptr, bd2, nullptr, h2, nullptr, BQ, LE, LE); // 13
    hmma_partial<<<dim3(1, 32, 8), 128, DSMEM>>>(h2, d3h, nullptr, bf, BQ, EE, LE, 256); // 14
    reduceK_kernel<<<(BQ * EE / 4 + 255) / 256, 256>>>(bf, bd3, x1, BQ * EE, EE, 8);    // 15
    dense_lrelu_32<<<dim3(2, 128), 256>>>(x1, Wd4, bd4, recon, nullptr, nullptr, BQ, 256, EE); // 16
}

// round 16
// speedup vs baseline: 1.1539x; 1.0336x over previous
#include <cuda_runtime.h>
#include <cuda_fp16.h>

#define BQ 4096
#define LE 2048
#define EE 128
#define KCB 2048
#define NROWS 65536

// ---- scratch ---------------------------------------------------------------
__device__ float  g_x1 [BQ * EE];
__device__ __half g_x1h[BQ * EE];
__device__ __half g_x1l[BQ * EE];
__device__ float  g_bf [BQ * LE];          // split-K partial scratch
__device__ __half g_h1 [BQ * LE];
__device__ __half g_l1 [BQ * LE];
__device__ __half g_h2 [BQ * LE];
__device__ __half g_l2 [BQ * LE];
__device__ __half g_w2h[LE * EE],  g_w2l[LE * EE];
__device__ __half g_w3h[LE * LE],  g_w3l[LE * LE];
__device__ __half g_w4h[LE * LE],  g_w4l[LE * LE];
__device__ __half g_d1h[LE * LE],  g_d1l[LE * LE];
__device__ __half g_d2h[LE * LE],  g_d2l[LE * LE];
__device__ __half g_d3h[EE * LE],  g_d3l[EE * LE];
__device__ __half g_cbh[KCB * EE], g_cbl[KCB * EE];
__device__ float  g_cbn[KCB];

__device__ __forceinline__ float lrelu(float v) { return fmaxf(v, 0.2f * v); }

__device__ __forceinline__ void f16split(float x, __half& h, __half& l) {
    h = __float2half_rn(x);
    l = __float2half_rn(x - __half2float(h));
}
__device__ __forceinline__ unsigned sm_u32(const void* p) {
    return (unsigned)__cvta_generic_to_shared(p);
}
__device__ __forceinline__ void cp16(unsigned s, const void* g) {
    asm volatile("cp.async.cg.shared.global [%0], [%1], 16;" :: "r"(s), "l"(g));
}
__device__ __forceinline__ void cp_commit() { asm volatile("cp.async.commit_group;"); }
template<int N> __device__ __forceinline__ void cp_wait() {
    asm volatile("cp.async.wait_group %0;" :: "n"(N));
}
__device__ __forceinline__ void hmma(float* c, const unsigned* a, const unsigned* b) {
    asm volatile(
        "mma.sync.aligned.m16n8k16.row.col.f32.f16.f16.f32 "
        "{%0,%1,%2,%3}, {%4,%5,%6,%7}, {%8,%9}, {%0,%1,%2,%3};"
        : "+f"(c[0]), "+f"(c[1]), "+f"(c[2]), "+f"(c[3])
        : "r"(a[0]), "r"(a[1]), "r"(a[2]), "r"(a[3]), "r"(b[0]), "r"(b[1]));
}
__device__ __forceinline__ void ldsm4(unsigned* r, unsigned addr) {
    asm volatile("ldmatrix.sync.aligned.m8n8.x4.shared.b16 {%0,%1,%2,%3}, [%4];"
        : "=r"(r[0]), "=r"(r[1]), "=r"(r[2]), "=r"(r[3]) : "r"(addr));
}
// ---- packed fp32x2 (skinny FFMA path) --------------------------------------
__device__ __forceinline__ unsigned long long pack2(float lo, float hi) {
    unsigned long long r;
    asm("mov.b64 %0, {%1, %2};" : "=l"(r) : "f"(lo), "f"(hi));
    return r;
}
__device__ __forceinline__ void fma2(unsigned long long& a,
                                     unsigned long long x, unsigned long long y) {
    asm("fma.rn.f32x2 %0, %1, %2, %0;" : "+l"(a) : "l"(x), "l"(y));
}
__device__ __forceinline__ float2 unpack2(unsigned long long v) {
    float lo, hi;
    asm("mov.b64 {%0, %1}, %2;" : "=f"(lo), "=f"(hi) : "l"(v));
    return make_float2(lo, hi);
}

// ---------------------------------------------------------------------------
// prep: W[K,N] -> [N,K] fp16 hi/lo, 64k x 32n tiles, half2 stores (128B rows)
// ---------------------------------------------------------------------------
__global__ void wtsplit_kernel(const float* __restrict__ W, __half* __restrict__ Th,
                               __half* __restrict__ Tl, int K, int N) {
    __shared__ float t[64][33];
    int n0 = blockIdx.x * 32, k0 = blockIdx.y * 64;
    int tx = threadIdx.x & 31, tr = threadIdx.x >> 5;
    for (int r = tr; r < 64; r += 8) t[r][tx] = W[(size_t)(k0 + r) * N + n0 + tx];
    __syncthreads();
    for (int r2 = tr; r2 < 32; r2 += 8) {
        __half h0, l0, h1, l1;
        f16split(t[2 * tx][r2], h0, l0);
        f16split(t[2 * tx + 1][r2], h1, l1);
        *(__half2*)&Th[(size_t)(n0 + r2) * K + k0 + 2 * tx] = __halves2half2(h0, h1);
        *(__half2*)&Tl[(size_t)(n0 + r2) * K + k0 + 2 * tx] = __halves2half2(l0, l1);
    }
}
__global__ void cbsplit_kernel(const float* __restrict__ cb, __half* __restrict__ hi,
                               __half* __restrict__ lo, float* __restrict__ nrm) {
    int n = blockIdx.x, e = threadIdx.x;
    float v = cb[n * EE + e];
    __half h, l; f16split(v, h, l);
    hi[n * EE + e] = h;
    lo[n * EE + e] = l;
    float q = v * v;
    #pragma unroll
    for (int o = 16; o > 0; o >>= 1) q += __shfl_xor_sync(0xFFFFFFFFu, q, o);
    __shared__ float ws[4];
    if ((e & 31) == 0) ws[e >> 5] = q;
    __syncthreads();
    if (e == 0) nrm[n] = ws[0] + ws[1] + ws[2] + ws[3];
}

// ---------------------------------------------------------------------------
// FP16 dense: 128 threads, 4 warps (2x2 of 64x64), BK=32.
// Pass count by null args: Al null -> drop Al*Bh; Bl null -> drop Ah*Bl.
// ---------------------------------------------------------------------------
#define DPIT   80
#define DPLANE 10240
#define DBUF   40960
#define DSMEM  81920

__global__ __launch_bounds__(128, 2) void hmma_dense(
    const __half* __restrict__ Ah, const __half* __restrict__ Al,
    const __half* __restrict__ Bh, const __half* __restrict__ Bl,
    const float* __restrict__ bias,
    float* __restrict__ Cf, __half* __restrict__ Ch, __half* __restrict__ Cl,
    int M, int N, int K)
{
    extern __shared__ char dsm[];
    unsigned smb = sm_u32(dsm);
    int tid = threadIdx.x, lane = tid & 31, wid = tid >> 5;
    int wm = wid >> 1, wn = wid & 1, g = lane >> 2, tig = lane & 3;
    int bm = blockIdx.y * 128, bn = blockIdx.x * 128;
    bool aLo = (Al != nullptr), bLo = (Bl != nullptr);

    const __half* P[4] = { Ah + (size_t)bm * K, aLo ? Al + (size_t)bm * K : nullptr,
                           Bh + (size_t)bn * K, bLo ? Bl + (size_t)bn * K : nullptr };

    float acc[4][8][4];
    #pragma unroll
    for (int i = 0; i < 4; i++)
        #pragma unroll
        for (int j = 0; j < 8; j++)
            #pragma unroll
            for (int q = 0; q < 4; q++) acc[i][j][q] = 0.f;

    unsigned aBase = (wm * 64 + (lane & 15)) * DPIT + ((lane >> 4) & 1) * 16;
    unsigned bBase = 2 * DPLANE + (wn * 64 + ((lane >> 4) & 1) * 8 + (lane & 7)) * DPIT
                     + ((lane >> 3) & 1) * 16;

    auto load_stage = [&](int u, int b) {
        #pragma unroll
        for (int i = 0; i < 16; i++) {
            int cid = i * 128 + tid;
            int p = cid >> 9, rem = cid & 511, row = rem >> 2, c = rem & 3;
            if (P[p])
                cp16(smb + b * DBUF + p * DPLANE + row * DPIT + c * 16,
                     P[p] + (size_t)row * K + u * 32 + c * 8);
        }
        cp_commit();
    };

    int S = K >> 5;
    load_stage(0, 0);
    load_stage(1, 1);

    for (int s = 0; s < S; s++) {
        int b = s & 1;
        if (s + 1 < S) cp_wait<1>(); else cp_wait<0>();
        __syncthreads();
        unsigned base = smb + b * DBUF;
        #pragma unroll
        for (int ko = 0; ko < 2; ko++) {
            unsigned Af[2][4][4], Bf[2][4][4];
            #pragma unroll
            for (int mt = 0; mt < 4; mt++) {
                ldsm4(Af[0][mt], base + aBase + mt * 16 * DPIT + ko * 32);
                if (aLo)
                    ldsm4(Af[1][mt], base + DPLANE + aBase + mt * 16 * DPIT + ko * 32);
            }
            #pragma unroll
            for (int np = 0; np < 4; np++) {
                ldsm4(Bf[0][np], base + bBase + np * 16 * DPIT + ko * 32);
                if (bLo)
                    ldsm4(Bf[1][np], base + DPLANE + bBase + np * 16 * DPIT + ko * 32);
            }
            if (aLo) {
                #pragma unroll
                for (int nt = 0; nt < 8; nt++)
                    #pragma unroll
                    for (int mt = 0; mt < 4; mt++)
                        hmma(acc[mt][nt], Af[1][mt], &Bf[0][nt >> 1][(nt & 1) * 2]);
            }
            if (bLo) {
                #pragma unroll
                for (int nt = 0; nt < 8; nt++)
                    #pragma unroll
                    for (int mt = 0; mt < 4; mt++)
                        hmma(acc[mt][nt], Af[0][mt], &Bf[1][nt >> 1][(nt & 1) * 2]);
            }
            #pragma unroll
            for (int nt = 0; nt < 8; nt++)
                #pragma unroll
                for (int mt = 0; mt < 4; mt++)
                    hmma(acc[mt][nt], Af[0][mt], &Bf[0][nt >> 1][(nt & 1) * 2]);
        }
        __syncthreads();
        if (s + 2 < S) load_stage(s + 2, b);
    }

    #pragma unroll
    for (int mt = 0; mt < 4; mt++) {
        int r0 = bm + wm * 64 + mt * 16 + g;
        int r1 = r0 + 8;
        #pragma unroll
        for (int nt = 0; nt < 8; nt++) {
            int cn = bn + wn * 64 + nt * 8 + 2 * tig;
            float2 bv = *(const float2*)&bias[cn];
            float o0 = lrelu(acc[mt][nt][0] + bv.x);
            float o1 = lrelu(acc[mt][nt][1] + bv.y);
            float o2 = lrelu(acc[mt][nt][2] + bv.x);
            float o3 = lrelu(acc[mt][nt][3] + bv.y);
            if (Cf) {
                *(float2*)&Cf[(size_t)r0 * N + cn] = make_float2(o0, o1);
                *(float2*)&Cf[(size_t)r1 * N + cn] = make_float2(o2, o3);
            }
            if (Ch) {
                __half h0, l0, h1, l1, h2v, l2v, h3, l3;
                f16split(o0, h0, l0); f16split(o1, h1, l1);
                f16split(o2, h2v, l2v); f16split(o3, h3, l3);
                *(__half2*)&Ch[(size_t)r0 * N + cn] = __halves2half2(h0, h1);
                *(__half2*)&Ch[(size_t)r1 * N + cn] = __halves2half2(h2v, h3);
                if (Cl) {
                    *(__half2*)&Cl[(size_t)r0 * N + cn] = __halves2half2(l0, l1);
                    *(__half2*)&Cl[(size_t)r1 * N + cn] = __halves2half2(l2v, l3);
                }
            }
        }
    }
}

// ---------------------------------------------------------------------------
// Split-K HMMA (Wd3): Bl null -> 1-pass. Raw fp32 partials.
// ---------------------------------------------------------------------------
__global__ __launch_bounds__(128, 2) void hmma_partial(
    const __half* __restrict__ Ah,
    const __half* __restrict__ Bh, const __half* __restrict__ Bl,
    float* __restrict__ Cp, int M, int N, int K, int KC)
{
    extern __shared__ char dsm[];
    unsigned smb = sm_u32(dsm);
    int tid = threadIdx.x, lane = tid & 31, wid = tid >> 5;
    int wm = wid >> 1, wn = wid & 1, g = lane >> 2, tig = lane & 3;
    int bm = blockIdx.y * 128, bn = blockIdx.x * 128;
    int kOff = blockIdx.z * KC;
    bool bLo = (Bl != nullptr);

    const __half* P[4] = { Ah + (size_t)bm * K + kOff, nullptr,
                           Bh + (size_t)bn * K + kOff, bLo ? Bl + (size_t)bn * K + kOff : nullptr };

    float acc[4][8][4];
    #pragma unroll
    for (int i = 0; i < 4; i++)
        #pragma unroll
        for (int j = 0; j < 8; j++)
            #pragma unroll
            for (int q = 0; q < 4; q++) acc[i][j][q] = 0.f;

    unsigned aBase = (wm * 64 + (lane & 15)) * DPIT + ((lane >> 4) & 1) * 16;
    unsigned bBase = 2 * DPLANE + (wn * 64 + ((lane >> 4) & 1) * 8 + (lane & 7)) * DPIT
                     + ((lane >> 3) & 1) * 16;

    auto load_stage = [&](int u, int b) {
        #pragma unroll
        for (int i = 0; i < 16; i++) {
            int cid = i * 128 + tid;
            int p = cid >> 9, rem = cid & 511, row = rem >> 2, c = rem & 3;
            if (P[p])
                cp16(smb + b * DBUF + p * DPLANE + row * DPIT + c * 16,
                     P[p] + (size_t)row * K + u * 32 + c * 8);
        }
        cp_commit();
    };

    int S = KC >> 5;
    load_stage(0, 0);
    load_stage(1, 1);

    for (int s = 0; s < S; s++) {
        int b = s & 1;
        if (s + 1 < S) cp_wait<1>(); else cp_wait<0>();
        __syncthreads();
        unsigned base = smb + b * DBUF;
        #pragma unroll
        for (int ko = 0; ko < 2; ko++) {
            unsigned Af[4][4], Bf[2][4][4];
            #pragma unroll
            for (int mt = 0; mt < 4; mt++)
                ldsm4(Af[mt], base + aBase + mt * 16 * DPIT + ko * 32);
            #pragma unroll
            for (int np = 0; np < 4; np++) {
                ldsm4(Bf[0][np], base + bBase + np * 16 * DPIT + ko * 32);
                if (bLo)
                    ldsm4(Bf[1][np], base + DPLANE + bBase + np * 16 * DPIT + ko * 32);
            }
            if (bLo) {
                #pragma unroll
                for (int nt = 0; nt < 8; nt++)
                    #pragma unroll
                    for (int mt = 0; mt < 4; mt++)
                        hmma(acc[mt][nt], Af[mt], &Bf[1][nt >> 1][(nt & 1) * 2]);
            }
            #pragma unroll
            for (int nt = 0; nt < 8; nt++)
                #pragma unroll
                for (int mt = 0; mt < 4; mt++)
                    hmma(acc[mt][nt], Af[mt], &Bf[0][nt >> 1][(nt & 1) * 2]);
        }
        __syncthreads();
        if (s + 2 < S) load_stage(s + 2, b);
    }

    size_t zbase = (size_t)blockIdx.z * M * N;
    #pragma unroll
    for (int mt = 0; mt < 4; mt++) {
        int r0 = bm + wm * 64 + mt * 16 + g;
        int r1 = r0 + 8;
        #pragma unroll
        for (int nt = 0; nt < 8; nt++) {
            int cn = bn + wn * 64 + nt * 8 + 2 * tig;
            *(float2*)&Cp[zbase + (size_t)r0 * N + cn] = make_float2(acc[mt][nt][0], acc[mt][nt][1]);
            *(float2*)&Cp[zbase + (size_t)r1 * N + cn] = make_float2(acc[mt][nt][2], acc[mt][nt][3]);
        }
    }
}

__global__ void reduceK_kernel(const float* __restrict__ Cp, const float* __restrict__ bias,
                               float* __restrict__ X, int MN, int N, int Z) {
    int i4 = blockIdx.x * 256 + threadIdx.x;
    int n4 = MN >> 2;
    if (i4 >= n4) return;
    const float4* C4 = (const float4*)Cp;
    float4 s = C4[i4];
    for (int z = 1; z < Z; z++) {
        float4 v = C4[(size_t)z * n4 + i4];
        s.x += v.x; s.y += v.y; s.z += v.z; s.w += v.w;
    }
    int col = (i4 * 4) & (N - 1);
    float4 bv = *(const float4*)&bias[col];
    float4 o;
    o.x = lrelu(s.x + bv.x); o.y = lrelu(s.y + bv.y);
    o.z = lrelu(s.z + bv.z); o.w = lrelu(s.w + bv.w);
    ((float4*)X)[i4] = o;
}

// ---------------------------------------------------------------------------
// 3xFP16 VQ: 256 threads, 8 warps (2x4 of 64x64), 256-codeword slabs,
// simple per-thread argmin, fused one-hot + gather.
// ---------------------------------------------------------------------------
#define BPLANE 20480
#define VBOFF  81920
#define VSMEM  (VBOFF + 2 * 2 * BPLANE)   // 163840

__global__ __launch_bounds__(256, 1) void hmma_vq(
    const __half* __restrict__ Ah, const __half* __restrict__ Al,
    const __half* __restrict__ cbh, const __half* __restrict__ cbl,
    const float* __restrict__ cbn, const float* __restrict__ cbf,
    float* __restrict__ quant, float* __restrict__ disc,
    __half* __restrict__ qh)
{
    extern __shared__ char dsm[];
    unsigned smb = sm_u32(dsm);
    __shared__ float sv[128][16];
    __shared__ int   si[128][16];
    __shared__ int   srow[128];
    int tid = threadIdx.x, lane = tid & 31, wid = tid >> 5;
    int wm = wid >> 2, wn = wid & 3, g = lane >> 2, tig = lane & 3;
    long bm = (long)blockIdx.x * 128;

    float acc[4][8][4];
    #pragma unroll
    for (int i = 0; i < 4; i++)
        #pragma unroll
        for (int j = 0; j < 8; j++)
            #pragma unroll
            for (int q = 0; q < 4; q++) acc[i][j][q] = 0.f;

    float bestv[8];
    int   besti[8];
    #pragma unroll
    for (int i = 0; i < 8; i++) { bestv[i] = 3.4e38f; besti[i] = 0; }

    unsigned aBase = (wm * 64 + (lane & 15)) * DPIT + ((lane >> 4) & 1) * 16;
    unsigned bBase = (wn * 64 + ((lane >> 4) & 1) * 8 + (lane & 7)) * DPIT
                     + ((lane >> 3) & 1) * 16;

    #pragma unroll
    for (int i = 0; i < 16; i++) {
        int cid = i * 256 + tid;
        int p = cid >> 9, rem = cid & 511, row = rem >> 2, c = rem & 3;
        const __half* base = (p >= 4) ? Al : Ah;
        cp16(smb + p * DPLANE + row * DPIT + c * 16,
             base + (bm + row) * 128 + (p & 3) * 32 + c * 8);
    }
    cp_commit();

    auto loadB = [&](int u, int b) {
        int slab = u >> 2, kc = u & 3;
        #pragma unroll
        for (int i = 0; i < 8; i++) {
            int cid = i * 256 + tid;
            int pl = cid >> 10, rem = cid & 1023, row = rem >> 2, c = rem & 3;
            const __half* base = pl ? cbl : cbh;
            cp16(smb + VBOFF + b * (2 * BPLANE) + pl * BPLANE + row * DPIT + c * 16,
                 base + (size_t)(slab * 256 + row) * 128 + kc * 32 + c * 8);
        }
        cp_commit();
    };
    loadB(0, 0);
    loadB(1, 1);

    for (int u = 0; u < 32; u++) {
        int b = u & 1, kc = u & 3;
        if (u + 1 < 32) cp_wait<1>(); else cp_wait<0>();
        __syncthreads();
        unsigned abase = smb + kc * DPLANE;
        unsigned bbase = smb + VBOFF + b * (2 * BPLANE);
        #pragma unroll
        for (int ko = 0; ko < 2; ko++) {
            unsigned Af[2][4][4], Bf[2][4][4];
            #pragma unroll
            for (int mt = 0; mt < 4; mt++) {
                ldsm4(Af[0][mt], abase + aBase + mt * 16 * DPIT + ko * 32);
                ldsm4(Af[1][mt], abase + 4 * DPLANE + aBase + mt * 16 * DPIT + ko * 32);
            }
            #pragma unroll
            for (int np = 0; np < 4; np++) {
                ldsm4(Bf[0][np], bbase + bBase + np * 16 * DPIT + ko * 32);
                ldsm4(Bf[1][np], bbase + BPLANE + bBase + np * 16 * DPIT + ko * 32);
            }
            #pragma unroll
            for (int nt = 0; nt < 8; nt++)
                #pragma unroll
                for (int mt = 0; mt < 4; mt++)
                    hmma(acc[mt][nt], Af[1][mt], &Bf[0][nt >> 1][(nt & 1) * 2]);
            #pragma unroll
            for (int nt = 0; nt < 8; nt++)
                #pragma unroll
                for (int mt = 0; mt < 4; mt++)
                    hmma(acc[mt][nt], Af[0][mt], &Bf[1][nt >> 1][(nt & 1) * 2]);
            #pragma unroll
            for (int nt = 0; nt < 8; nt++)
                #pragma unroll
                for (int mt = 0; mt < 4; mt++)
                    hmma(acc[mt][nt], Af[0][mt], &Bf[0][nt >> 1][(nt & 1) * 2]);
        }
        if (kc == 3) {
            int c0 = (u >> 2) * 256;
            #pragma unroll
            for (int mt = 0; mt < 4; mt++) {
                #pragma unroll
                for (int nt = 0; nt < 8; nt++) {
                    int cn = c0 + wn * 64 + nt * 8 + 2 * tig;
                    float2 nn = *(const float2*)&cbn[cn];
                    float* a = acc[mt][nt];
                    float d0 = nn.x - 2.f * a[0];
                    if (d0 < bestv[mt * 2]) { bestv[mt * 2] = d0; besti[mt * 2] = cn; }
                    float d1 = nn.y - 2.f * a[1];
                    if (d1 < bestv[mt * 2]) { bestv[mt * 2] = d1; besti[mt * 2] = cn + 1; }
                    float d2 = nn.x - 2.f * a[2];
                    if (d2 < bestv[mt * 2 + 1]) { bestv[mt * 2 + 1] = d2; besti[mt * 2 + 1] = cn; }
                    float d3 = nn.y - 2.f * a[3];
                    if (d3 < bestv[mt * 2 + 1]) { bestv[mt * 2 + 1] = d3; besti[mt * 2 + 1] = cn + 1; }
                    a[0] = a[1] = a[2] = a[3] = 0.f;
                }
            }
        }
        __syncthreads();
        if (u + 2 < 32) loadB(u + 2, b);
    }

    #pragma unroll
    for (int mt = 0; mt < 4; mt++) {
        int r0 = wm * 64 + mt * 16 + g;
        int col = wn * 4 + tig;
        sv[r0][col] = bestv[mt * 2];         si[r0][col] = besti[mt * 2];
        sv[r0 + 8][col] = bestv[mt * 2 + 1]; si[r0 + 8][col] = besti[mt * 2 + 1];
    }
    __syncthreads();
    if (tid < 128) {
        float bv = sv[tid][0];
        int   bi = si[tid][0];
        #pragma unroll
        for (int t = 1; t < 16; t++) {
            float v = sv[tid][t];
            int  ix = si[tid][t];
            if (v < bv || (v == bv && ix < bi)) { bv = v; bi = ix; }
        }
        srow[tid] = bi;
    }
    __syncthreads();

    for (int it = tid; it < 128 * 512; it += 256) {
        int rr = it >> 9, c4 = it & 511;
        float4 z = make_float4(0.f, 0.f, 0.f, 0.f);
        int bi = srow[rr];
        if ((bi >> 2) == c4) ((float*)&z)[bi & 3] = 1.0f;
        ((float4*)disc)[(bm + rr) * 512 + c4] = z;
    }
    for (int it = tid; it < 128 * 32; it += 256) {
        int rr = it >> 5, c = it & 31;
        ((float4*)quant)[(bm + rr) * 32 + c] = ((const float4*)cbf)[srow[rr] * 32 + c];
    }
    for (int it = tid; it < 128 * 16; it += 256) {
        int rr = it >> 4, c = it & 15;
        ((uint4*)qh)[(bm + rr) * 16 + c] = ((const uint4*)cbh)[srow[rr] * 16 + c];
    }
}

// ---------------------------------------------------------------------------
// FFMA skinny layers (32x128 tile), exact fp32, optional fp16 hi/lo epilogue
// ---------------------------------------------------------------------------
__global__ __launch_bounds__(256) void dense_lrelu_32(
    const float* __restrict__ A, const float* __restrict__ W,
    const float* __restrict__ bias, float* __restrict__ C,
    __half* __restrict__ Chi, __half* __restrict__ Clo,
    int M, int N, int K)
{
    __shared__ float As[2][8][32];
    __shared__ float Bs[2][8][128];
    int tid = threadIdx.x, tx = tid & 15, ty = tid >> 4;
    int bm = blockIdx.y * 32, bn = blockIdx.x * 128;
    int arow = tid >> 3, acol = tid & 7;
    int wrow = tid >> 5, wcol = (tid & 31) * 4;

    unsigned long long acc[2][4];
    #pragma unroll
    for (int i = 0; i < 2; i++)
        #pragma unroll
        for (int j = 0; j < 4; j++) acc[i][j] = 0ULL;

    const float* Ap = A + (size_t)(bm + arow) * K + acol;
    const float* Wp = W + (size_t)wrow * N + bn + wcol;
    size_t wstep = (size_t)8 * N;
    int T = K >> 3;
    float areg = *Ap;  Ap += 8;
    cp16(sm_u32(&Bs[0][wrow][wcol]), Wp); Wp += wstep;
    cp_commit();

    for (int i = 0; i < T; i++) {
        int cur = i & 1;
        As[cur][acol][arow] = areg;
        if (i + 1 < T) {
            areg = *Ap;  Ap += 8;
            cp16(sm_u32(&Bs[cur ^ 1][wrow][wcol]), Wp); Wp += wstep;
            cp_commit();
            cp_wait<1>();
        } else cp_wait<0>();
        __syncthreads();
        #pragma unroll
        for (int kk = 0; kk < 8; kk++) {
            float2 a2 = *(const float2*)&As[cur][kk][ty * 2];
            float4 b0 = *(const float4*)&Bs[cur][kk][tx * 4];
            float4 b1 = *(const float4*)&Bs[cur][kk][64 + tx * 4];
            unsigned long long bp[4] = { pack2(b0.x, b0.y), pack2(b0.z, b0.w),
                                         pack2(b1.x, b1.y), pack2(b1.z, b1.w) };
            unsigned long long a0 = pack2(a2.x, a2.x), a1 = pack2(a2.y, a2.y);
            fma2(acc[0][0], a0, bp[0]); fma2(acc[0][1], a0, bp[1]);
            fma2(acc[0][2], a0, bp[2]); fma2(acc[0][3], a0, bp[3]);
            fma2(acc[1][0], a1, bp[0]); fma2(acc[1][1], a1, bp[1]);
            fma2(acc[1][2], a1, bp[2]); fma2(acc[1][3], a1, bp[3]);
        }
        __syncthreads();
    }

    float bb0[4], bb1[4];
    #pragma unroll
    for (int j = 0; j < 4; j++) {
        bb0[j] = __ldg(&bias[bn + tx * 4 + j]);
        bb1[j] = __ldg(&bias[bn + 64 + tx * 4 + j]);
    }
    #pragma unroll
    for (int i = 0; i < 2; i++) {
        int r = bm + ty * 2 + i;
        float2 p0 = unpack2(acc[i][0]), p1 = unpack2(acc[i][1]);
        float2 p2 = unpack2(acc[i][2]), p3 = unpack2(acc[i][3]);
        float o[8];
        o[0] = lrelu(p0.x + bb0[0]); o[1] = lrelu(p0.y + bb0[1]);
        o[2] = lrelu(p1.x + bb0[2]); o[3] = lrelu(p1.y + bb0[3]);
        o[4] = lrelu(p2.x + bb1[0]); o[5] = lrelu(p2.y + bb1[1]);
        o[6] = lrelu(p3.x + bb1[2]); o[7] = lrelu(p3.y + bb1[3]);
        *(float4*)&C[(size_t)r * N + bn + tx * 4]      = make_float4(o[0], o[1], o[2], o[3]);
        *(float4*)&C[(size_t)r * N + bn + 64 + tx * 4] = make_float4(o[4], o[5], o[6], o[7]);
        if (Chi) {
            #pragma unroll
            for (int j = 0; j < 8; j++) {
                int cc = bn + ((j < 4) ? 0 : 64) + tx * 4 + (j & 3);
                __half h, l; f16split(o[j], h, l);
                Chi[(size_t)r * N + cc] = h;
                Clo[(size_t)r * N + cc] = l;
            }
        }
    }
}

// ---------------------------------------------------------------------------
extern "C" void kernel_launch(void* const* d_in, const int* in_sizes, int n_in,
                              void* d_out, int out_size) {
    const float* cond = (const float*)d_in[0];
    const float* cb   = (const float*)d_in[1];
    const float* We1  = (const float*)d_in[2];  const float* be1 = (const float*)d_in[3];
    const float* We2  = (const float*)d_in[4];  const float* be2 = (const float*)d_in[5];
    const float* We3  = (const float*)d_in[6];  const float* be3 = (const float*)d_in[7];
    const float* We4  = (const float*)d_in[8];  const float* be4 = (const float*)d_in[9];
    const float* Wd1  = (const float*)d_in[10]; const float* bd1 = (const float*)d_in[11];
    const float* Wd2  = (const float*)d_in[12]; const float* bd2 = (const float*)d_in[13];
    const float* Wd3  = (const float*)d_in[14]; const float* bd3 = (const float*)d_in[15];
    const float* Wd4  = (const float*)d_in[16]; const float* bd4 = (const float*)d_in[17];

    float* out   = (float*)d_out;
    float* recon = out;
    float* enc   = recon + (size_t)BQ * 256;
    float* disc  = enc   + (size_t)BQ * LE;
    float* quant = disc  + (size_t)NROWS * KCB;

    float *x1, *bf, *cbn;
    __half *x1h, *x1l, *h1, *l1, *h2, *l2;
    __half *w2h, *w2l, *w3h, *w3l, *w4h, *w4l, *d1h, *d1l, *d2h, *d2l, *d3h, *d3l, *cbh, *cbl;
    cudaGetSymbolAddress((void**)&x1,  g_x1);  cudaGetSymbolAddress((void**)&bf,  g_bf);
    cudaGetSymbolAddress((void**)&x1h, g_x1h); cudaGetSymbolAddress((void**)&x1l, g_x1l);
    cudaGetSymbolAddress((void**)&h1,  g_h1);  cudaGetSymbolAddress((void**)&l1,  g_l1);
    cudaGetSymbolAddress((void**)&h2,  g_h2);  cudaGetSymbolAddress((void**)&l2,  g_l2);
    cudaGetSymbolAddress((void**)&w2h, g_w2h); cudaGetSymbolAddress((void**)&w2l, g_w2l);
    cudaGetSymbolAddress((void**)&w3h, g_w3h); cudaGetSymbolAddress((void**)&w3l, g_w3l);
    cudaGetSymbolAddress((void**)&w4h, g_w4h); cudaGetSymbolAddress((void**)&w4l, g_w4l);
    cudaGetSymbolAddress((void**)&d1h, g_d1h); cudaGetSymbolAddress((void**)&d1l, g_d1l);
    cudaGetSymbolAddress((void**)&d2h, g_d2h); cudaGetSymbolAddress((void**)&d2l, g_d2l);
    cudaGetSymbolAddress((void**)&d3h, g_d3h); cudaGetSymbolAddress((void**)&d3l, g_d3l);
    cudaGetSymbolAddress((void**)&cbh, g_cbh); cudaGetSymbolAddress((void**)&cbl, g_cbl);
    cudaGetSymbolAddress((void**)&cbn, g_cbn);

    static cudaStream_t s2 = nullptr;
    static cudaEvent_t evF, evW2, evW3, evW4, evPrep;
    if (!s2) {
        cudaStreamCreateWithFlags(&s2, cudaStreamNonBlocking);
        cudaEventCreateWithFlags(&evF,    cudaEventDisableTiming);
        cudaEventCreateWithFlags(&evW2,   cudaEventDisableTiming);
        cudaEventCreateWithFlags(&evW3,   cudaEventDisableTiming);
        cudaEventCreateWithFlags(&evW4,   cudaEventDisableTiming);
        cudaEventCreateWithFlags(&evPrep, cudaEventDisableTiming);
        cudaFuncSetAttribute(hmma_dense,   cudaFuncAttributeMaxDynamicSharedMemorySize, DSMEM);
        cudaFuncSetAttribute(hmma_partial, cudaFuncAttributeMaxDynamicSharedMemorySize, DSMEM);
        cudaFuncSetAttribute(hmma_vq,      cudaFuncAttributeMaxDynamicSharedMemorySize, VSMEM);
    }

    // fork prep stream off the (capture) default stream
    cudaEventRecord(evF, 0);
    cudaStreamWaitEvent(s2, evF, 0);

    // prep on s2 (depends only on kernel inputs)
    wtsplit_kernel<<<dim3(64, 2),  256, 0, s2>>>(We2, w2h, w2l, EE, LE);
    cudaEventRecord(evW2, s2);
    wtsplit_kernel<<<dim3(64, 32), 256, 0, s2>>>(We3, w3h, w3l, LE, LE);
    cudaEventRecord(evW3, s2);
    wtsplit_kernel<<<dim3(64, 32), 256, 0, s2>>>(We4, w4h, w4l, LE, LE);
    cudaEventRecord(evW4, s2);
    cbsplit_kernel<<<KCB, 128, 0, s2>>>(cb, cbh, cbl, cbn);
    wtsplit_kernel<<<dim3(64, 32), 256, 0, s2>>>(Wd1, d1h, d1l, LE, LE);
    wtsplit_kernel<<<dim3(64, 32), 256, 0, s2>>>(Wd2, d2h, d2l, LE, LE);
    wtsplit_kernel<<<dim3(4, 32),  256, 0, s2>>>(Wd3, d3h, d3l, LE, EE);
    cudaEventRecord(evPrep, s2);

    // main chain on default stream
    dense_lrelu_32<<<dim3(1, 128), 256>>>(cond, We1, be1, x1, x1h, x1l, BQ, EE, 256);
    cudaStreamWaitEvent(0, evW2, 0);
    hmma_dense<<<dim3(16, 32), 128, DSMEM>>>(x1h, x1l, w2h, w2l, be2, nullptr, h1, l1, BQ, LE, EE);
    cudaStreamWaitEvent(0, evW3, 0);
    hmma_dense<<<dim3(16, 32), 128, DSMEM>>>(h1, l1, w3h, w3l, be3, nullptr, h2, l2, BQ, LE, LE);
    cudaStreamWaitEvent(0, evW4, 0);
    hmma_dense<<<dim3(16, 32), 128, DSMEM>>>(h2, l2, w4h, w4l, be4, enc, h1, l1, BQ, LE, LE);
    cudaStreamWaitEvent(0, evPrep, 0);   // codebook + decoder splits done (long finished by now)
    // VQ: 3-pass, simple argmin
    hmma_vq<<<NROWS / 128, 256, VSMEM>>>(h1, l1, cbh, cbl, cbn, cb, quant, disc, h2);
    // decoder: Wd1 1-pass, Wd2 1-pass, Wd3 split-K 1-pass, Wd4 exact FFMA
    hmma_dense<<<dim3(16, 32), 128, DSMEM>>>(h2, nullptr, d1h, nullptr, bd1, nullptr, h1, nullptr, BQ, LE, LE);
    hmma_dense<<<dim3(16, 32), 128, DSMEM>>>(h1, nullptr, d2h, nullptr, bd2, nullptr, h2, nullptr, BQ, LE, LE);
    hmma_partial<<<dim3(1, 32, 8), 128, DSMEM>>>(h2, d3h, nullptr, bf, BQ, EE, LE, 256);
    reduceK_kernel<<<(BQ * EE / 4 + 255) / 256, 256>>>(bf, bd3, x1, BQ * EE, EE, 8);
    dense_lrelu_32<<<dim3(2, 128), 256>>>(x1, Wd4, bd4, recon, nullptr, nullptr, BQ, 256, EE);
}

// round 17
// speedup vs baseline: 1.2273x; 1.0636x over previous
#include <cuda_runtime.h>
#include <cuda_fp16.h>

#define BQ 4096
#define LE 2048
#define EE 128
#define KCB 2048
#define NROWS 65536

// ---- scratch ---------------------------------------------------------------
__device__ float  g_x1 [BQ * EE];
__device__ __half g_x1h[BQ * EE];
__device__ __half g_x1l[BQ * EE];
__device__ float  g_bf [BQ * LE];          // split-K partial scratch
__device__ __half g_h1 [BQ * LE];
__device__ __half g_l1 [BQ * LE];
__device__ __half g_h2 [BQ * LE];
__device__ __half g_l2 [BQ * LE];
__device__ __half g_w2h[LE * EE],  g_w2l[LE * EE];
__device__ __half g_w3h[LE * LE],  g_w3l[LE * LE];
__device__ __half g_w4h[LE * LE],  g_w4l[LE * LE];
__device__ __half g_d1h[LE * LE],  g_d1l[LE * LE];
__device__ __half g_d2h[LE * LE],  g_d2l[LE * LE];
__device__ __half g_d3h[EE * LE],  g_d3l[EE * LE];
__device__ __half g_cbh[KCB * EE], g_cbl[KCB * EE];
__device__ float  g_cbn[KCB];
__device__ int    g_idx[NROWS];            // VQ argmin indices

__device__ __forceinline__ float lrelu(float v) { return fmaxf(v, 0.2f * v); }

__device__ __forceinline__ void f16split(float x, __half& h, __half& l) {
    h = __float2half_rn(x);
    l = __float2half_rn(x - __half2float(h));
}
__device__ __forceinline__ unsigned sm_u32(const void* p) {
    return (unsigned)__cvta_generic_to_shared(p);
}
__device__ __forceinline__ void cp16(unsigned s, const void* g) {
    asm volatile("cp.async.cg.shared.global [%0], [%1], 16;" :: "r"(s), "l"(g));
}
__device__ __forceinline__ void cp_commit() { asm volatile("cp.async.commit_group;"); }
template<int N> __device__ __forceinline__ void cp_wait() {
    asm volatile("cp.async.wait_group %0;" :: "n"(N));
}
__device__ __forceinline__ void hmma(float* c, const unsigned* a, const unsigned* b) {
    asm volatile(
        "mma.sync.aligned.m16n8k16.row.col.f32.f16.f16.f32 "
        "{%0,%1,%2,%3}, {%4,%5,%6,%7}, {%8,%9}, {%0,%1,%2,%3};"
        : "+f"(c[0]), "+f"(c[1]), "+f"(c[2]), "+f"(c[3])
        : "r"(a[0]), "r"(a[1]), "r"(a[2]), "r"(a[3]), "r"(b[0]), "r"(b[1]));
}
__device__ __forceinline__ void ldsm4(unsigned* r, unsigned addr) {
    asm volatile("ldmatrix.sync.aligned.m8n8.x4.shared.b16 {%0,%1,%2,%3}, [%4];"
        : "=r"(r[0]), "=r"(r[1]), "=r"(r[2]), "=r"(r[3]) : "r"(addr));
}
// ---- packed fp32x2 (skinny FFMA path) --------------------------------------
__device__ __forceinline__ unsigned long long pack2(float lo, float hi) {
    unsigned long long r;
    asm("mov.b64 %0, {%1, %2};" : "=l"(r) : "f"(lo), "f"(hi));
    return r;
}
__device__ __forceinline__ void fma2(unsigned long long& a,
                                     unsigned long long x, unsigned long long y) {
    asm("fma.rn.f32x2 %0, %1, %2, %0;" : "+l"(a) : "l"(x), "l"(y));
}
__device__ __forceinline__ float2 unpack2(unsigned long long v) {
    float lo, hi;
    asm("mov.b64 {%0, %1}, %2;" : "=f"(lo), "=f"(hi) : "l"(v));
    return make_float2(lo, hi);
}

// ---------------------------------------------------------------------------
// prep: W[K,N] -> [N,K] fp16 hi/lo, 64k x 32n tiles, half2 stores (128B rows)
// ---------------------------------------------------------------------------
__global__ void wtsplit_kernel(const float* __restrict__ W, __half* __restrict__ Th,
                               __half* __restrict__ Tl, int K, int N) {
    __shared__ float t[64][33];
    int n0 = blockIdx.x * 32, k0 = blockIdx.y * 64;
    int tx = threadIdx.x & 31, tr = threadIdx.x >> 5;
    for (int r = tr; r < 64; r += 8) t[r][tx] = W[(size_t)(k0 + r) * N + n0 + tx];
    __syncthreads();
    for (int r2 = tr; r2 < 32; r2 += 8) {
        __half h0, l0, h1, l1;
        f16split(t[2 * tx][r2], h0, l0);
        f16split(t[2 * tx + 1][r2], h1, l1);
        *(__half2*)&Th[(size_t)(n0 + r2) * K + k0 + 2 * tx] = __halves2half2(h0, h1);
        *(__half2*)&Tl[(size_t)(n0 + r2) * K + k0 + 2 * tx] = __halves2half2(l0, l1);
    }
}
__global__ void cbsplit_kernel(const float* __restrict__ cb, __half* __restrict__ hi,
                               __half* __restrict__ lo, float* __restrict__ nrm) {
    int n = blockIdx.x, e = threadIdx.x;
    float v = cb[n * EE + e];
    __half h, l; f16split(v, h, l);
    hi[n * EE + e] = h;
    lo[n * EE + e] = l;
    float q = v * v;
    #pragma unroll
    for (int o = 16; o > 0; o >>= 1) q += __shfl_xor_sync(0xFFFFFFFFu, q, o);
    __shared__ float ws[4];
    if ((e & 31) == 0) ws[e >> 5] = q;
    __syncthreads();
    if (e == 0) nrm[n] = ws[0] + ws[1] + ws[2] + ws[3];
}
// one-hot slab writer: reads g_idx, writes disc (runs concurrent with decoder)
__global__ void onehot_kernel(const int* __restrict__ idx, float* __restrict__ disc) {
    long bm = (long)blockIdx.x * 128;
    int tid = threadIdx.x;
    for (int it = tid; it < 128 * 512; it += 256) {
        int rr = it >> 9, c4 = it & 511;
        float4 z = make_float4(0.f, 0.f, 0.f, 0.f);
        int bi = idx[bm + rr];
        if ((bi >> 2) == c4) ((float*)&z)[bi & 3] = 1.0f;
        ((float4*)disc)[(bm + rr) * 512 + c4] = z;
    }
}

// ---------------------------------------------------------------------------
// FP16 dense: 128 threads, 4 warps (2x2 of 64x64), BK=32.
// Pass count by null args: Al null -> drop Al*Bh; Bl null -> drop Ah*Bl.
// ---------------------------------------------------------------------------
#define DPIT   80
#define DPLANE 10240
#define DBUF   40960
#define DSMEM  81920

__global__ __launch_bounds__(128, 2) void hmma_dense(
    const __half* __restrict__ Ah, const __half* __restrict__ Al,
    const __half* __restrict__ Bh, const __half* __restrict__ Bl,
    const float* __restrict__ bias,
    float* __restrict__ Cf, __half* __restrict__ Ch, __half* __restrict__ Cl,
    int M, int N, int K)
{
    extern __shared__ char dsm[];
    unsigned smb = sm_u32(dsm);
    int tid = threadIdx.x, lane = tid & 31, wid = tid >> 5;
    int wm = wid >> 1, wn = wid & 1, g = lane >> 2, tig = lane & 3;
    int bm = blockIdx.y * 128, bn = blockIdx.x * 128;
    bool aLo = (Al != nullptr), bLo = (Bl != nullptr);

    const __half* P[4] = { Ah + (size_t)bm * K, aLo ? Al + (size_t)bm * K : nullptr,
                           Bh + (size_t)bn * K, bLo ? Bl + (size_t)bn * K : nullptr };

    float acc[4][8][4];
    #pragma unroll
    for (int i = 0; i < 4; i++)
        #pragma unroll
        for (int j = 0; j < 8; j++)
            #pragma unroll
            for (int q = 0; q < 4; q++) acc[i][j][q] = 0.f;

    unsigned aBase = (wm * 64 + (lane & 15)) * DPIT + ((lane >> 4) & 1) * 16;
    unsigned bBase = 2 * DPLANE + (wn * 64 + ((lane >> 4) & 1) * 8 + (lane & 7)) * DPIT
                     + ((lane >> 3) & 1) * 16;

    auto load_stage = [&](int u, int b) {
        #pragma unroll
        for (int i = 0; i < 16; i++) {
            int cid = i * 128 + tid;
            int p = cid >> 9, rem = cid & 511, row = rem >> 2, c = rem & 3;
            if (P[p])
                cp16(smb + b * DBUF + p * DPLANE + row * DPIT + c * 16,
                     P[p] + (size_t)row * K + u * 32 + c * 8);
        }
        cp_commit();
    };

    int S = K >> 5;
    load_stage(0, 0);
    load_stage(1, 1);

    for (int s = 0; s < S; s++) {
        int b = s & 1;
        if (s + 1 < S) cp_wait<1>(); else cp_wait<0>();
        __syncthreads();
        unsigned base = smb + b * DBUF;
        #pragma unroll
        for (int ko = 0; ko < 2; ko++) {
            unsigned Af[2][4][4], Bf[2][4][4];
            #pragma unroll
            for (int mt = 0; mt < 4; mt++) {
                ldsm4(Af[0][mt], base + aBase + mt * 16 * DPIT + ko * 32);
                if (aLo)
                    ldsm4(Af[1][mt], base + DPLANE + aBase + mt * 16 * DPIT + ko * 32);
            }
            #pragma unroll
            for (int np = 0; np < 4; np++) {
                ldsm4(Bf[0][np], base + bBase + np * 16 * DPIT + ko * 32);
                if (bLo)
                    ldsm4(Bf[1][np], base + DPLANE + bBase + np * 16 * DPIT + ko * 32);
            }
            if (aLo) {
                #pragma unroll
                for (int nt = 0; nt < 8; nt++)
                    #pragma unroll
                    for (int mt = 0; mt < 4; mt++)
                        hmma(acc[mt][nt], Af[1][mt], &Bf[0][nt >> 1][(nt & 1) * 2]);
            }
            if (bLo) {
                #pragma unroll
                for (int nt = 0; nt < 8; nt++)
                    #pragma unroll
                    for (int mt = 0; mt < 4; mt++)
                        hmma(acc[mt][nt], Af[0][mt], &Bf[1][nt >> 1][(nt & 1) * 2]);
            }
            #pragma unroll
            for (int nt = 0; nt < 8; nt++)
                #pragma unroll
                for (int mt = 0; mt < 4; mt++)
                    hmma(acc[mt][nt], Af[0][mt], &Bf[0][nt >> 1][(nt & 1) * 2]);
        }
        __syncthreads();
        if (s + 2 < S) load_stage(s + 2, b);
    }

    #pragma unroll
    for (int mt = 0; mt < 4; mt++) {
        int r0 = bm + wm * 64 + mt * 16 + g;
        int r1 = r0 + 8;
        #pragma unroll
        for (int nt = 0; nt < 8; nt++) {
            int cn = bn + wn * 64 + nt * 8 + 2 * tig;
            float2 bv = *(const float2*)&bias[cn];
            float o0 = lrelu(acc[mt][nt][0] + bv.x);
            float o1 = lrelu(acc[mt][nt][1] + bv.y);
            float o2 = lrelu(acc[mt][nt][2] + bv.x);
            float o3 = lrelu(acc[mt][nt][3] + bv.y);
            if (Cf) {
                *(float2*)&Cf[(size_t)r0 * N + cn] = make_float2(o0, o1);
                *(float2*)&Cf[(size_t)r1 * N + cn] = make_float2(o2, o3);
            }
            if (Ch) {
                __half h0, l0, h1, l1, h2v, l2v, h3, l3;
                f16split(o0, h0, l0); f16split(o1, h1, l1);
                f16split(o2, h2v, l2v); f16split(o3, h3, l3);
                *(__half2*)&Ch[(size_t)r0 * N + cn] = __halves2half2(h0, h1);
                *(__half2*)&Ch[(size_t)r1 * N + cn] = __halves2half2(h2v, h3);
                if (Cl) {
                    *(__half2*)&Cl[(size_t)r0 * N + cn] = __halves2half2(l0, l1);
                    *(__half2*)&Cl[(size_t)r1 * N + cn] = __halves2half2(l2v, l3);
                }
            }
        }
    }
}

// ---------------------------------------------------------------------------
// Split-K HMMA (Wd3): Bl null -> 1-pass. Raw fp32 partials.
// ---------------------------------------------------------------------------
__global__ __launch_bounds__(128, 2) void hmma_partial(
    const __half* __restrict__ Ah,
    const __half* __restrict__ Bh, const __half* __restrict__ Bl,
    float* __restrict__ Cp, int M, int N, int K, int KC)
{
    extern __shared__ char dsm[];
    unsigned smb = sm_u32(dsm);
    int tid = threadIdx.x, lane = tid & 31, wid = tid >> 5;
    int wm = wid >> 1, wn = wid & 1, g = lane >> 2, tig = lane & 3;
    int bm = blockIdx.y * 128, bn = blockIdx.x * 128;
    int kOff = blockIdx.z * KC;
    bool bLo = (Bl != nullptr);

    const __half* P[4] = { Ah + (size_t)bm * K + kOff, nullptr,
                           Bh + (size_t)bn * K + kOff, bLo ? Bl + (size_t)bn * K + kOff : nullptr };

    float acc[4][8][4];
    #pragma unroll
    for (int i = 0; i < 4; i++)
        #pragma unroll
        for (int j = 0; j < 8; j++)
            #pragma unroll
            for (int q = 0; q < 4; q++) acc[i][j][q] = 0.f;

    unsigned aBase = (wm * 64 + (lane & 15)) * DPIT + ((lane >> 4) & 1) * 16;
    unsigned bBase = 2 * DPLANE + (wn * 64 + ((lane >> 4) & 1) * 8 + (lane & 7)) * DPIT
                     + ((lane >> 3) & 1) * 16;

    auto load_stage = [&](int u, int b) {
        #pragma unroll
        for (int i = 0; i < 16; i++) {
            int cid = i * 128 + tid;
            int p = cid >> 9, rem = cid & 511, row = rem >> 2, c = rem & 3;
            if (P[p])
                cp16(smb + b * DBUF + p * DPLANE + row * DPIT + c * 16,
                     P[p] + (size_t)row * K + u * 32 + c * 8);
        }
        cp_commit();
    };

    int S = KC >> 5;
    load_stage(0, 0);
    load_stage(1, 1);

    for (int s = 0; s < S; s++) {
        int b = s & 1;
        if (s + 1 < S) cp_wait<1>(); else cp_wait<0>();
        __syncthreads();
        unsigned base = smb + b * DBUF;
        #pragma unroll
        for (int ko = 0; ko < 2; ko++) {
            unsigned Af[4][4], Bf[2][4][4];
            #pragma unroll
            for (int mt = 0; mt < 4; mt++)
                ldsm4(Af[mt], base + aBase + mt * 16 * DPIT + ko * 32);
            #pragma unroll
            for (int np = 0; np < 4; np++) {
                ldsm4(Bf[0][np], base + bBase + np * 16 * DPIT + ko * 32);
                if (bLo)
                    ldsm4(Bf[1][np], base + DPLANE + bBase + np * 16 * DPIT + ko * 32);
            }
            if (bLo) {
                #pragma unroll
                for (int nt = 0; nt < 8; nt++)
                    #pragma unroll
                    for (int mt = 0; mt < 4; mt++)
                        hmma(acc[mt][nt], Af[mt], &Bf[1][nt >> 1][(nt & 1) * 2]);
            }
            #pragma unroll
            for (int nt = 0; nt < 8; nt++)
                #pragma unroll
                for (int mt = 0; mt < 4; mt++)
                    hmma(acc[mt][nt], Af[mt], &Bf[0][nt >> 1][(nt & 1) * 2]);
        }
        __syncthreads();
        if (s + 2 < S) load_stage(s + 2, b);
    }

    size_t zbase = (size_t)blockIdx.z * M * N;
    #pragma unroll
    for (int mt = 0; mt < 4; mt++) {
        int r0 = bm + wm * 64 + mt * 16 + g;
        int r1 = r0 + 8;
        #pragma unroll
        for (int nt = 0; nt < 8; nt++) {
            int cn = bn + wn * 64 + nt * 8 + 2 * tig;
            *(float2*)&Cp[zbase + (size_t)r0 * N + cn] = make_float2(acc[mt][nt][0], acc[mt][nt][1]);
            *(float2*)&Cp[zbase + (size_t)r1 * N + cn] = make_float2(acc[mt][nt][2], acc[mt][nt][3]);
        }
    }
}

__global__ void reduceK_kernel(const float* __restrict__ Cp, const float* __restrict__ bias,
                               float* __restrict__ X, int MN, int N, int Z) {
    int i4 = blockIdx.x * 256 + threadIdx.x;
    int n4 = MN >> 2;
    if (i4 >= n4) return;
    const float4* C4 = (const float4*)Cp;
    float4 s = C4[i4];
    for (int z = 1; z < Z; z++) {
        float4 v = C4[(size_t)z * n4 + i4];
        s.x += v.x; s.y += v.y; s.z += v.z; s.w += v.w;
    }
    int col = (i4 * 4) & (N - 1);
    float4 bv = *(const float4*)&bias[col];
    float4 o;
    o.x = lrelu(s.x + bv.x); o.y = lrelu(s.y + bv.y);
    o.z = lrelu(s.z + bv.z); o.w = lrelu(s.w + bv.w);
    ((float4*)X)[i4] = o;
}

// ---------------------------------------------------------------------------
// 3xFP16 VQ: 256 threads, 8 warps (2x4 of 64x64), 256-codeword slabs,
// simple per-thread argmin. Writes indices + quant + qh (one-hot deferred).
// ---------------------------------------------------------------------------
#define BPLANE 20480
#define VBOFF  81920
#define VSMEM  (VBOFF + 2 * 2 * BPLANE)   // 163840

__global__ __launch_bounds__(256, 1) void hmma_vq(
    const __half* __restrict__ Ah, const __half* __restrict__ Al,
    const __half* __restrict__ cbh, const __half* __restrict__ cbl,
    const float* __restrict__ cbn, const float* __restrict__ cbf,
    float* __restrict__ quant, int* __restrict__ idxout,
    __half* __restrict__ qh)
{
    extern __shared__ char dsm[];
    unsigned smb = sm_u32(dsm);
    __shared__ float sv[128][16];
    __shared__ int   si[128][16];
    __shared__ int   srow[128];
    int tid = threadIdx.x, lane = tid & 31, wid = tid >> 5;
    int wm = wid >> 2, wn = wid & 3, g = lane >> 2, tig = lane & 3;
    long bm = (long)blockIdx.x * 128;

    float acc[4][8][4];
    #pragma unroll
    for (int i = 0; i < 4; i++)
        #pragma unroll
        for (int j = 0; j < 8; j++)
            #pragma unroll
            for (int q = 0; q < 4; q++) acc[i][j][q] = 0.f;

    float bestv[8];
    int   besti[8];
    #pragma unroll
    for (int i = 0; i < 8; i++) { bestv[i] = 3.4e38f; besti[i] = 0; }

    unsigned aBase = (wm * 64 + (lane & 15)) * DPIT + ((lane >> 4) & 1) * 16;
    unsigned bBase = (wn * 64 + ((lane >> 4) & 1) * 8 + (lane & 7)) * DPIT
                     + ((lane >> 3) & 1) * 16;

    #pragma unroll
    for (int i = 0; i < 16; i++) {
        int cid = i * 256 + tid;
        int p = cid >> 9, rem = cid & 511, row = rem >> 2, c = rem & 3;
        const __half* base = (p >= 4) ? Al : Ah;
        cp16(smb + p * DPLANE + row * DPIT + c * 16,
             base + (bm + row) * 128 + (p & 3) * 32 + c * 8);
    }
    cp_commit();

    auto loadB = [&](int u, int b) {
        int slab = u >> 2, kc = u & 3;
        #pragma unroll
        for (int i = 0; i < 8; i++) {
            int cid = i * 256 + tid;
            int pl = cid >> 10, rem = cid & 1023, row = rem >> 2, c = rem & 3;
            const __half* base = pl ? cbl : cbh;
            cp16(smb + VBOFF + b * (2 * BPLANE) + pl * BPLANE + row * DPIT + c * 16,
                 base + (size_t)(slab * 256 + row) * 128 + kc * 32 + c * 8);
        }
        cp_commit();
    };
    loadB(0, 0);
    loadB(1, 1);

    for (int u = 0; u < 32; u++) {
        int b = u & 1, kc = u & 3;
        if (u + 1 < 32) cp_wait<1>(); else cp_wait<0>();
        __syncthreads();
        unsigned abase = smb + kc * DPLANE;
        unsigned bbase = smb + VBOFF + b * (2 * BPLANE);
        #pragma unroll
        for (int ko = 0; ko < 2; ko++) {
            unsigned Af[2][4][4], Bf[2][4][4];
            #pragma unroll
            for (int mt = 0; mt < 4; mt++) {
                ldsm4(Af[0][mt], abase + aBase + mt * 16 * DPIT + ko * 32);
                ldsm4(Af[1][mt], abase + 4 * DPLANE + aBase + mt * 16 * DPIT + ko * 32);
            }
            #pragma unroll
            for (int np = 0; np < 4; np++) {
                ldsm4(Bf[0][np], bbase + bBase + np * 16 * DPIT + ko * 32);
                ldsm4(Bf[1][np], bbase + BPLANE + bBase + np * 16 * DPIT + ko * 32);
            }
            #pragma unroll
            for (int nt = 0; nt < 8; nt++)
                #pragma unroll
                for (int mt = 0; mt < 4; mt++)
                    hmma(acc[mt][nt], Af[1][mt], &Bf[0][nt >> 1][(nt & 1) * 2]);
            #pragma unroll
            for (int nt = 0; nt < 8; nt++)
                #pragma unroll
                for (int mt = 0; mt < 4; mt++)
                    hmma(acc[mt][nt], Af[0][mt], &Bf[1][nt >> 1][(nt & 1) * 2]);
            #pragma unroll
            for (int nt = 0; nt < 8; nt++)
                #pragma unroll
                for (int mt = 0; mt < 4; mt++)
                    hmma(acc[mt][nt], Af[0][mt], &Bf[0][nt >> 1][(nt & 1) * 2]);
        }
        if (kc == 3) {
            int c0 = (u >> 2) * 256;
            #pragma unroll
            for (int mt = 0; mt < 4; mt++) {
                #pragma unroll
                for (int nt = 0; nt < 8; nt++) {
                    int cn = c0 + wn * 64 + nt * 8 + 2 * tig;
                    float2 nn = *(const float2*)&cbn[cn];
                    float* a = acc[mt][nt];
                    float d0 = nn.x - 2.f * a[0];
                    if (d0 < bestv[mt * 2]) { bestv[mt * 2] = d0; besti[mt * 2] = cn; }
                    float d1 = nn.y - 2.f * a[1];
                    if (d1 < bestv[mt * 2]) { bestv[mt * 2] = d1; besti[mt * 2] = cn + 1; }
                    float d2 = nn.x - 2.f * a[2];
                    if (d2 < bestv[mt * 2 + 1]) { bestv[mt * 2 + 1] = d2; besti[mt * 2 + 1] = cn; }
                    float d3 = nn.y - 2.f * a[3];
                    if (d3 < bestv[mt * 2 + 1]) { bestv[mt * 2 + 1] = d3; besti[mt * 2 + 1] = cn + 1; }
                    a[0] = a[1] = a[2] = a[3] = 0.f;
                }
            }
        }
        __syncthreads();
        if (u + 2 < 32) loadB(u + 2, b);
    }

    #pragma unroll
    for (int mt = 0; mt < 4; mt++) {
        int r0 = wm * 64 + mt * 16 + g;
        int col = wn * 4 + tig;
        sv[r0][col] = bestv[mt * 2];         si[r0][col] = besti[mt * 2];
        sv[r0 + 8][col] = bestv[mt * 2 + 1]; si[r0 + 8][col] = besti[mt * 2 + 1];
    }
    __syncthreads();
    if (tid < 128) {
        float bv = sv[tid][0];
        int   bi = si[tid][0];
        #pragma unroll
        for (int t = 1; t < 16; t++) {
            float v = sv[tid][t];
            int  ix = si[tid][t];
            if (v < bv || (v == bv && ix < bi)) { bv = v; bi = ix; }
        }
        srow[tid] = bi;
        idxout[bm + tid] = bi;
    }
    __syncthreads();

    // quantized fp32 + hi plane (one-hot deferred to onehot_kernel)
    for (int it = tid; it < 128 * 32; it += 256) {
        int rr = it >> 5, c = it & 31;
        ((float4*)quant)[(bm + rr) * 32 + c] = ((const float4*)cbf)[srow[rr] * 32 + c];
    }
    for (int it = tid; it < 128 * 16; it += 256) {
        int rr = it >> 4, c = it & 15;
        ((uint4*)qh)[(bm + rr) * 16 + c] = ((const uint4*)cbh)[srow[rr] * 16 + c];
    }
}

// ---------------------------------------------------------------------------
// FFMA skinny layers (32x128 tile), exact fp32, optional fp16 hi/lo epilogue
// ---------------------------------------------------------------------------
__global__ __launch_bounds__(256) void dense_lrelu_32(
    const float* __restrict__ A, const float* __restrict__ W,
    const float* __restrict__ bias, float* __restrict__ C,
    __half* __restrict__ Chi, __half* __restrict__ Clo,
    int M, int N, int K)
{
    __shared__ float As[2][8][32];
    __shared__ float Bs[2][8][128];
    int tid = threadIdx.x, tx = tid & 15, ty = tid >> 4;
    int bm = blockIdx.y * 32, bn = blockIdx.x * 128;
    int arow = tid >> 3, acol = tid & 7;
    int wrow = tid >> 5, wcol = (tid & 31) * 4;

    unsigned long long acc[2][4];
    #pragma unroll
    for (int i = 0; i < 2; i++)
        #pragma unroll
        for (int j = 0; j < 4; j++) acc[i][j] = 0ULL;

    const float* Ap = A + (size_t)(bm + arow) * K + acol;
    const float* Wp = W + (size_t)wrow * N + bn + wcol;
    size_t wstep = (size_t)8 * N;
    int T = K >> 3;
    float areg = *Ap;  Ap += 8;
    cp16(sm_u32(&Bs[0][wrow][wcol]), Wp); Wp += wstep;
    cp_commit();

    for (int i = 0; i < T; i++) {
        int cur = i & 1;
        As[cur][acol][arow] = areg;
        if (i + 1 < T) {
            areg = *Ap;  Ap += 8;
            cp16(sm_u32(&Bs[cur ^ 1][wrow][wcol]), Wp); Wp += wstep;
            cp_commit();
            cp_wait<1>();
        } else cp_wait<0>();
        __syncthreads();
        #pragma unroll
        for (int kk = 0; kk < 8; kk++) {
            float2 a2 = *(const float2*)&As[cur][kk][ty * 2];
            float4 b0 = *(const float4*)&Bs[cur][kk][tx * 4];
            float4 b1 = *(const float4*)&Bs[cur][kk][64 + tx * 4];
            unsigned long long bp[4] = { pack2(b0.x, b0.y), pack2(b0.z, b0.w),
                                         pack2(b1.x, b1.y), pack2(b1.z, b1.w) };
            unsigned long long a0 = pack2(a2.x, a2.x), a1 = pack2(a2.y, a2.y);
            fma2(acc[0][0], a0, bp[0]); fma2(acc[0][1], a0, bp[1]);
            fma2(acc[0][2], a0, bp[2]); fma2(acc[0][3], a0, bp[3]);
            fma2(acc[1][0], a1, bp[0]); fma2(acc[1][1], a1, bp[1]);
            fma2(acc[1][2], a1, bp[2]); fma2(acc[1][3], a1, bp[3]);
        }
        __syncthreads();
    }

    float bb0[4], bb1[4];
    #pragma unroll
    for (int j = 0; j < 4; j++) {
        bb0[j] = __ldg(&bias[bn + tx * 4 + j]);
        bb1[j] = __ldg(&bias[bn + 64 + tx * 4 + j]);
    }
    #pragma unroll
    for (int i = 0; i < 2; i++) {
        int r = bm + ty * 2 + i;
        float2 p0 = unpack2(acc[i][0]), p1 = unpack2(acc[i][1]);
        float2 p2 = unpack2(acc[i][2]), p3 = unpack2(acc[i][3]);
        float o[8];
        o[0] = lrelu(p0.x + bb0[0]); o[1] = lrelu(p0.y + bb0[1]);
        o[2] = lrelu(p1.x + bb0[2]); o[3] = lrelu(p1.y + bb0[3]);
        o[4] = lrelu(p2.x + bb1[0]); o[5] = lrelu(p2.y + bb1[1]);
        o[6] = lrelu(p3.x + bb1[2]); o[7] = lrelu(p3.y + bb1[3]);
        *(float4*)&C[(size_t)r * N + bn + tx * 4]      = make_float4(o[0], o[1], o[2], o[3]);
        *(float4*)&C[(size_t)r * N + bn + 64 + tx * 4] = make_float4(o[4], o[5], o[6], o[7]);
        if (Chi) {
            #pragma unroll
            for (int j = 0; j < 8; j++) {
                int cc = bn + ((j < 4) ? 0 : 64) + tx * 4 + (j & 3);
                __half h, l; f16split(o[j], h, l);
                Chi[(size_t)r * N + cc] = h;
                Clo[(size_t)r * N + cc] = l;
            }
        }
    }
}

// ---------------------------------------------------------------------------
extern "C" void kernel_launch(void* const* d_in, const int* in_sizes, int n_in,
                              void* d_out, int out_size) {
    const float* cond = (const float*)d_in[0];
    const float* cb   = (const float*)d_in[1];
    const float* We1  = (const float*)d_in[2];  const float* be1 = (const float*)d_in[3];
    const float* We2  = (const float*)d_in[4];  const float* be2 = (const float*)d_in[5];
    const float* We3  = (const float*)d_in[6];  const float* be3 = (const float*)d_in[7];
    const float* We4  = (const float*)d_in[8];  const float* be4 = (const float*)d_in[9];
    const float* Wd1  = (const float*)d_in[10]; const float* bd1 = (const float*)d_in[11];
    const float* Wd2  = (const float*)d_in[12]; const float* bd2 = (const float*)d_in[13];
    const float* Wd3  = (const float*)d_in[14]; const float* bd3 = (const float*)d_in[15];
    const float* Wd4  = (const float*)d_in[16]; const float* bd4 = (const float*)d_in[17];

    float* out   = (float*)d_out;
    float* recon = out;
    float* enc   = recon + (size_t)BQ * 256;
    float* disc  = enc   + (size_t)BQ * LE;
    float* quant = disc  + (size_t)NROWS * KCB;

    float *x1, *bf, *cbn;
    int *idx;
    __half *x1h, *x1l, *h1, *l1, *h2, *l2;
    __half *w2h, *w2l, *w3h, *w3l, *w4h, *w4l, *d1h, *d1l, *d2h, *d2l, *d3h, *d3l, *cbh, *cbl;
    cudaGetSymbolAddress((void**)&x1,  g_x1);  cudaGetSymbolAddress((void**)&bf,  g_bf);
    cudaGetSymbolAddress((void**)&x1h, g_x1h); cudaGetSymbolAddress((void**)&x1l, g_x1l);
    cudaGetSymbolAddress((void**)&h1,  g_h1);  cudaGetSymbolAddress((void**)&l1,  g_l1);
    cudaGetSymbolAddress((void**)&h2,  g_h2);  cudaGetSymbolAddress((void**)&l2,  g_l2);
    cudaGetSymbolAddress((void**)&w2h, g_w2h); cudaGetSymbolAddress((void**)&w2l, g_w2l);
    cudaGetSymbolAddress((void**)&w3h, g_w3h); cudaGetSymbolAddress((void**)&w3l, g_w3l);
    cudaGetSymbolAddress((void**)&w4h, g_w4h); cudaGetSymbolAddress((void**)&w4l, g_w4l);
    cudaGetSymbolAddress((void**)&d1h, g_d1h); cudaGetSymbolAddress((void**)&d1l, g_d1l);
    cudaGetSymbolAddress((void**)&d2h, g_d2h); cudaGetSymbolAddress((void**)&d2l, g_d2l);
    cudaGetSymbolAddress((void**)&d3h, g_d3h); cudaGetSymbolAddress((void**)&d3l, g_d3l);
    cudaGetSymbolAddress((void**)&cbh, g_cbh); cudaGetSymbolAddress((void**)&cbl, g_cbl);
    cudaGetSymbolAddress((void**)&cbn, g_cbn); cudaGetSymbolAddress((void**)&idx, g_idx);

    static cudaStream_t s2 = nullptr;
    static cudaEvent_t evF, evW2, evW3, evW4, evPrep, evVQ, evOH;
    if (!s2) {
        cudaStreamCreateWithFlags(&s2, cudaStreamNonBlocking);
        cudaEventCreateWithFlags(&evF,    cudaEventDisableTiming);
        cudaEventCreateWithFlags(&evW2,   cudaEventDisableTiming);
        cudaEventCreateWithFlags(&evW3,   cudaEventDisableTiming);
        cudaEventCreateWithFlags(&evW4,   cudaEventDisableTiming);
        cudaEventCreateWithFlags(&evPrep, cudaEventDisableTiming);
        cudaEventCreateWithFlags(&evVQ,   cudaEventDisableTiming);
        cudaEventCreateWithFlags(&evOH,   cudaEventDisableTiming);
        cudaFuncSetAttribute(hmma_dense,   cudaFuncAttributeMaxDynamicSharedMemorySize, DSMEM);
        cudaFuncSetAttribute(hmma_partial, cudaFuncAttributeMaxDynamicSharedMemorySize, DSMEM);
        cudaFuncSetAttribute(hmma_vq,      cudaFuncAttributeMaxDynamicSharedMemorySize, VSMEM);
    }

    // fork prep stream off the (capture) default stream
    cudaEventRecord(evF, 0);
    cudaStreamWaitEvent(s2, evF, 0);

    // prep on s2 (depends only on kernel inputs)
    wtsplit_kernel<<<dim3(64, 2),  256, 0, s2>>>(We2, w2h, w2l, EE, LE);
    cudaEventRecord(evW2, s2);
    wtsplit_kernel<<<dim3(64, 32), 256, 0, s2>>>(We3, w3h, w3l, LE, LE);
    cudaEventRecord(evW3, s2);
    wtsplit_kernel<<<dim3(64, 32), 256, 0, s2>>>(We4, w4h, w4l, LE, LE);
    cudaEventRecord(evW4, s2);
    cbsplit_kernel<<<KCB, 128, 0, s2>>>(cb, cbh, cbl, cbn);
    wtsplit_kernel<<<dim3(64, 32), 256, 0, s2>>>(Wd1, d1h, d1l, LE, LE);
    wtsplit_kernel<<<dim3(64, 32), 256, 0, s2>>>(Wd2, d2h, d2l, LE, LE);
    wtsplit_kernel<<<dim3(4, 32),  256, 0, s2>>>(Wd3, d3h, d3l, LE, EE);
    cudaEventRecord(evPrep, s2);

    // main chain on default stream
    dense_lrelu_32<<<dim3(1, 128), 256>>>(cond, We1, be1, x1, x1h, x1l, BQ, EE, 256);
    cudaStreamWaitEvent(0, evW2, 0);
    hmma_dense<<<dim3(16, 32), 128, DSMEM>>>(x1h, x1l, w2h, w2l, be2, nullptr, h1, l1, BQ, LE, EE);
    cudaStreamWaitEvent(0, evW3, 0);
    hmma_dense<<<dim3(16, 32), 128, DSMEM>>>(h1, l1, w3h, w3l, be3, nullptr, h2, l2, BQ, LE, LE);
    cudaStreamWaitEvent(0, evW4, 0);
    hmma_dense<<<dim3(16, 32), 128, DSMEM>>>(h2, l2, w4h, w4l, be4, enc, h1, l1, BQ, LE, LE);
    cudaStreamWaitEvent(0, evPrep, 0);
    // VQ: 3-pass, simple argmin; writes idx + quant + qh (no one-hot)
    hmma_vq<<<NROWS / 128, 256, VSMEM>>>(h1, l1, cbh, cbl, cbn, cb, quant, idx, h2);
    cudaEventRecord(evVQ, 0);
    // one-hot slab on s2, concurrent with decoder
    cudaStreamWaitEvent(s2, evVQ, 0);
    onehot_kernel<<<NROWS / 128, 256, 0, s2>>>(idx, disc);
    cudaEventRecord(evOH, s2);
    // decoder on default stream
    hmma_dense<<<dim3(16, 32), 128, DSMEM>>>(h2, nullptr, d1h, nullptr, bd1, nullptr, h1, nullptr, BQ, LE, LE);
    hmma_dense<<<dim3(16, 32), 128, DSMEM>>>(h1, nullptr, d2h, nullptr, bd2, nullptr, h2, nullptr, BQ, LE, LE);
    hmma_partial<<<dim3(1, 32, 8), 128, DSMEM>>>(h2, d3h, nullptr, bf, BQ, EE, LE, 256);
    reduceK_kernel<<<(BQ * EE / 4 + 255) / 256, 256>>>(bf, bd3, x1, BQ * EE, EE, 8);
    dense_lrelu_32<<<dim3(2, 128), 256>>>(x1, Wd4, bd4, recon, nullptr, nullptr, BQ, 256, EE);
    // join one-hot branch before capture ends
    cudaStreamWaitEvent(0, evOH, 0);
}